// round 9
// baseline (speedup 1.0000x reference)
#include <cuda_runtime.h>
#include <cuda_bf16.h>
#include <cstdint>

#define B   32
#define L   1024
#define D   256
#define INV_TEMP (1.0f/16.0f)

// ---------------------------------------------------------------------------
// Scratch
// ---------------------------------------------------------------------------
__device__ __nv_bfloat16 g_qh [B * L * D];
__device__ __nv_bfloat16 g_ql [B * L * D];
__device__ __nv_bfloat16 g_qth[B * D * L];
__device__ __nv_bfloat16 g_qtl[B * D * L];
__device__ __nv_bfloat16 g_ph [B * L * L];
__device__ __nv_bfloat16 g_pl [B * L * L];

// upper-triangle block pair decode (8x8 blocks -> 36 pairs)
__constant__ uint8_t c_bi[36] = {0,0,0,0,0,0,0,0, 1,1,1,1,1,1,1, 2,2,2,2,2,2,
                                 3,3,3,3,3, 4,4,4,4, 5,5,5, 6,6, 7};
__constant__ uint8_t c_bj[36] = {0,1,2,3,4,5,6,7, 1,2,3,4,5,6,7, 2,3,4,5,6,7,
                                 3,4,5,6,7, 4,5,6,7, 5,6,7, 6,7, 7};

__device__ __forceinline__ float neg_inf() { return __int_as_float(0xff800000); }

__device__ __forceinline__ uint32_t smem_to_u32(const void* p) {
    uint32_t a;
    asm("{ .reg .u64 t; cvta.to.shared.u64 t, %1; cvt.u32.u64 %0, t; }" : "=r"(a) : "l"(p));
    return a;
}

#define SWZ(x) ((x) ^ (((x) >> 3) & 0x70))

__device__ __forceinline__ void ldsm_x4(uint32_t& r0, uint32_t& r1, uint32_t& r2, uint32_t& r3,
                                        uint32_t addr) {
    asm volatile("ldmatrix.sync.aligned.m8n8.x4.shared.b16 {%0,%1,%2,%3}, [%4];"
                 : "=r"(r0), "=r"(r1), "=r"(r2), "=r"(r3) : "r"(addr));
}

__device__ __forceinline__ void mma_bf16(float& c0, float& c1, float& c2, float& c3,
                                         uint32_t a0, uint32_t a1, uint32_t a2, uint32_t a3,
                                         uint32_t b0, uint32_t b1) {
    asm volatile("mma.sync.aligned.m16n8k16.row.col.f32.bf16.bf16.f32 "
                 "{%0,%1,%2,%3}, {%4,%5,%6,%7}, {%8,%9}, {%0,%1,%2,%3};"
                 : "+f"(c0), "+f"(c1), "+f"(c2), "+f"(c3)
                 : "r"(a0), "r"(a1), "r"(a2), "r"(a3), "r"(b0), "r"(b1));
}

#define CP_ASYNC_16(dst, src) \
    asm volatile("cp.async.cg.shared.global [%0], [%1], 16;" :: "r"(dst), "l"(src))
#define CP_ASYNC_COMMIT() asm volatile("cp.async.commit_group;" ::: "memory")
#define CP_ASYNC_WAIT(n)  asm volatile("cp.async.wait_group %0;" :: "n"(n) : "memory")

// ---------------------------------------------------------------------------
// Kernel A: split q -> bf16 hi/lo + transposed hi/lo copies.
// ---------------------------------------------------------------------------
__global__ void __launch_bounds__(256) split_q_kernel(const float* __restrict__ q) {
    const int b  = blockIdx.z;
    const int d0 = blockIdx.x * 32;
    const int l0 = blockIdx.y * 32;
    const float* Q = q + (size_t)b * L * D;
    __shared__ float t[32][33];
    const int tx = threadIdx.x, ty = threadIdx.y;

    #pragma unroll
    for (int i = 0; i < 4; i++) {
        const int r = ty + i * 8;
        const float v = Q[(size_t)(l0 + r) * D + d0 + tx];
        t[r][tx] = v;
        __nv_bfloat16 h  = __float2bfloat16(v);
        __nv_bfloat16 lo = __float2bfloat16(v - __bfloat162float(h));
        const size_t idx = (size_t)b * L * D + (size_t)(l0 + r) * D + d0 + tx;
        g_qh[idx] = h;
        g_ql[idx] = lo;
    }
    __syncthreads();
    #pragma unroll
    for (int i = 0; i < 4; i++) {
        const int r = ty + i * 8;
        const float v = t[tx][r];
        __nv_bfloat16 h  = __float2bfloat16(v);
        __nv_bfloat16 lo = __float2bfloat16(v - __bfloat162float(h));
        const size_t idx = (size_t)b * D * L + (size_t)(d0 + r) * L + l0 + tx;
        g_qth[idx] = h;
        g_qtl[idx] = lo;
    }
}

// ---------------------------------------------------------------------------
// Generic tile loader: ROWS x 64 bf16, 128B swizzled rows, NT threads.
// ---------------------------------------------------------------------------
template <int ROWS, int NT>
__device__ __forceinline__ void issue_tile(const __nv_bfloat16* __restrict__ src,
                                           int row0, int ld, int k0,
                                           uint32_t smem_tile, int tid) {
    #pragma unroll
    for (int i = 0; i < (ROWS * 8) / NT; i++) {
        const int chunk = tid + i * NT;
        const int row = chunk >> 3;
        const int c16 = chunk & 7;
        const __nv_bfloat16* g = src + (size_t)(row0 + row) * ld + k0 + c16 * 8;
        CP_ASYNC_16(smem_tile + SWZ((uint32_t)(row * 128 + c16 * 16)), g);
    }
}

// ===========================================================================
// GEMM1 (symmetric): CTA 128x128, 512 threads, 16 warps (4x4),
// warp tile 32x32, 3-stage cp.async. smem 3 x 64KB = 192KB.
// ===========================================================================
#define TILE_BYTES 16384
#define STAGE_BYTES (4 * TILE_BYTES)
#define NSTAGE 3
#define GEMM1_SMEM (NSTAGE * STAGE_BYTES)

__device__ __forceinline__ void issue_stage128(
        const __nv_bfloat16* pAh, const __nv_bfloat16* pAl,
        int m0, int n0, int k0, uint32_t st, int tid) {
    issue_tile<128, 512>(pAh, m0, D, k0, st + 0 * TILE_BYTES, tid);
    issue_tile<128, 512>(pAl, m0, D, k0, st + 1 * TILE_BYTES, tid);
    issue_tile<128, 512>(pAh, n0, D, k0, st + 2 * TILE_BYTES, tid);
    issue_tile<128, 512>(pAl, n0, D, k0, st + 3 * TILE_BYTES, tid);
    CP_ASYNC_COMMIT();
}

__global__ void __launch_bounds__(512, 1)
gemm_qqt_sym_kernel(const __nv_bfloat16* __restrict__ Qh, const __nv_bfloat16* __restrict__ Ql,
                    float* __restrict__ S) {
    extern __shared__ char smem[];
    const uint32_t sb = smem_to_u32(smem);
    const int tid = threadIdx.x, wid = tid >> 5, lid = tid & 31;
    const int b  = blockIdx.z;
    const int bi = c_bi[blockIdx.x];
    const int bj = c_bj[blockIdx.x];
    const int m0 = bi * 128;
    const int n0 = bj * 128;

    const __nv_bfloat16* pAh = Qh + (size_t)b * L * D;
    const __nv_bfloat16* pAl = Ql + (size_t)b * L * D;

    const int rowbase = (wid & 3) * 32;     // 4x4 warp grid, tile 32x32
    const int colbase = (wid >> 2) * 32;
    const int lrow = lid & 15;
    const uint32_t lkoff = (uint32_t)((lid >> 4) * 16);

    float acc[2][4][4];
    #pragma unroll
    for (int mt = 0; mt < 2; mt++)
        #pragma unroll
        for (int nt = 0; nt < 4; nt++)
            #pragma unroll
            for (int r = 0; r < 4; r++) acc[mt][nt][r] = 0.0f;

    const int nch = D >> 6;   // 4
    issue_stage128(pAh, pAl, m0, n0, 0, sb, tid);
    issue_stage128(pAh, pAl, m0, n0, 64, sb + STAGE_BYTES, tid);

    for (int c = 0; c < nch; c++) {
        if (c + 1 < nch) { CP_ASYNC_WAIT(1); } else { CP_ASYNC_WAIT(0); }
        __syncthreads();
        if (c + 2 < nch) {
            issue_stage128(pAh, pAl, m0, n0, (c + 2) << 6,
                           sb + (uint32_t)((c + 2) % NSTAGE) * STAGE_BYTES, tid);
        }

        const uint32_t st = sb + (uint32_t)(c % NSTAGE) * STAGE_BYTES;
        const uint32_t aH = st + 0 * TILE_BYTES;
        const uint32_t aL = st + 1 * TILE_BYTES;
        const uint32_t bH = st + 2 * TILE_BYTES;
        const uint32_t bL = st + 3 * TILE_BYTES;

        #pragma unroll
        for (int ks = 0; ks < 4; ks++) {
            const uint32_t kb = (uint32_t)(ks * 32) + lkoff;
            uint32_t ah[2][4], al[2][4];
            #pragma unroll
            for (int mt = 0; mt < 2; mt++) {
                const uint32_t boff = (uint32_t)((rowbase + mt * 16 + lrow) * 128) + kb;
                ldsm_x4(ah[mt][0], ah[mt][1], ah[mt][2], ah[mt][3], aH + SWZ(boff));
                ldsm_x4(al[mt][0], al[mt][1], al[mt][2], al[mt][3], aL + SWZ(boff));
            }
            #pragma unroll
            for (int np = 0; np < 2; np++) {
                const uint32_t boff = (uint32_t)((colbase + np * 16 + lrow) * 128) + kb;
                uint32_t bh[4], bl[4];
                ldsm_x4(bh[0], bh[1], bh[2], bh[3], bH + SWZ(boff));
                ldsm_x4(bl[0], bl[1], bl[2], bl[3], bL + SWZ(boff));
                #pragma unroll
                for (int mt = 0; mt < 2; mt++) {
                    float* c0 = acc[mt][np * 2 + 0];
                    float* c1 = acc[mt][np * 2 + 1];
                    mma_bf16(c0[0], c0[1], c0[2], c0[3],
                             ah[mt][0], ah[mt][1], ah[mt][2], ah[mt][3], bh[0], bh[2]);
                    mma_bf16(c1[0], c1[1], c1[2], c1[3],
                             ah[mt][0], ah[mt][1], ah[mt][2], ah[mt][3], bh[1], bh[3]);
                    mma_bf16(c0[0], c0[1], c0[2], c0[3],
                             ah[mt][0], ah[mt][1], ah[mt][2], ah[mt][3], bl[0], bl[2]);
                    mma_bf16(c1[0], c1[1], c1[2], c1[3],
                             ah[mt][0], ah[mt][1], ah[mt][2], ah[mt][3], bl[1], bl[3]);
                    mma_bf16(c0[0], c0[1], c0[2], c0[3],
                             al[mt][0], al[mt][1], al[mt][2], al[mt][3], bh[0], bh[2]);
                    mma_bf16(c1[0], c1[1], c1[2], c1[3],
                             al[mt][0], al[mt][1], al[mt][2], al[mt][3], bh[1], bh[3]);
                }
            }
        }
    }
    __syncthreads();

    // mask + scale
    #pragma unroll
    for (int mt = 0; mt < 2; mt++)
        #pragma unroll
        for (int nt = 0; nt < 4; nt++)
            #pragma unroll
            for (int r = 0; r < 4; r++) {
                float v = acc[mt][nt][r];
                acc[mt][nt][r] = (v == 0.0f) ? neg_inf() : v * INV_TEMP;
            }

    float* pS = S + (size_t)b * L * L;
    const int trow = lid >> 2;
    const int tcol = (lid & 3) * 2;

    // direct tile write
    #pragma unroll
    for (int mt = 0; mt < 2; mt++) {
        #pragma unroll
        for (int nt = 0; nt < 4; nt++) {
            const int row = m0 + rowbase + mt * 16 + trow;
            const int col = n0 + colbase + nt * 8 + tcol;
            *(float2*)(pS + (size_t)row * L + col) =
                make_float2(acc[mt][nt][0], acc[mt][nt][1]);
            *(float2*)(pS + (size_t)(row + 8) * L + col) =
                make_float2(acc[mt][nt][2], acc[mt][nt][3]);
        }
    }

    if (bi != bj) {
        // stage transpose in smem (128 x 132 floats), then coalesced write
        float* smemT = (float*)smem;
        #pragma unroll
        for (int mt = 0; mt < 2; mt++) {
            #pragma unroll
            for (int nt = 0; nt < 4; nt++) {
                const int i0 = rowbase + mt * 16 + trow;
                const int j0 = colbase + nt * 8 + tcol;
                smemT[(j0 + 0) * 132 + i0]     = acc[mt][nt][0];
                smemT[(j0 + 1) * 132 + i0]     = acc[mt][nt][1];
                smemT[(j0 + 0) * 132 + i0 + 8] = acc[mt][nt][2];
                smemT[(j0 + 1) * 132 + i0 + 8] = acc[mt][nt][3];
            }
        }
        __syncthreads();
        const int j       = tid >> 2;           // 0..127
        const int quarter = (tid & 3) * 32;     // 0,32,64,96
        float* dst = pS + (size_t)(n0 + j) * L + m0 + quarter;
        const float* srcrow = smemT + j * 132 + quarter;
        #pragma unroll
        for (int u = 0; u < 8; u++) {
            *(float4*)(dst + u * 4) = *(const float4*)(srcrow + u * 4);
        }
    }
}

// ===========================================================================
// GEMM2 (unchanged from R8): O = P @ Q. CTA 64x128, 8 warps (2x4),
// warp tile 32x32, 2-stage, 96KB smem -> 2 CTAs/SM.
// ===========================================================================
#define PV_TA 8192
#define PV_TB 16384
#define PV_STAGE (2 * PV_TA + 2 * PV_TB)
#define PV_SMEM (2 * PV_STAGE)
#define PV_AH 0
#define PV_AL PV_TA
#define PV_BH (2 * PV_TA)
#define PV_BL (2 * PV_TA + PV_TB)

__device__ __forceinline__ void pv_issue_stage(
        const __nv_bfloat16* pAh, const __nv_bfloat16* pAl,
        const __nv_bfloat16* pBh, const __nv_bfloat16* pBl,
        int m0, int n0, int k0, uint32_t st, int tid) {
    issue_tile<64, 256>(pAh, m0, L, k0, st + PV_AH, tid);
    issue_tile<64, 256>(pAl, m0, L, k0, st + PV_AL, tid);
    issue_tile<128, 256>(pBh, n0, L, k0, st + PV_BH, tid);
    issue_tile<128, 256>(pBl, n0, L, k0, st + PV_BL, tid);
    CP_ASYNC_COMMIT();
}

__global__ void __launch_bounds__(256, 2)
gemm_pv_kernel(const __nv_bfloat16* __restrict__ Ph, const __nv_bfloat16* __restrict__ Pl,
               const __nv_bfloat16* __restrict__ Bh, const __nv_bfloat16* __restrict__ Bl,
               float* __restrict__ O) {
    extern __shared__ char smem[];
    const uint32_t sb = smem_to_u32(smem);
    const int tid = threadIdx.x, wid = tid >> 5, lid = tid & 31;
    const int b  = blockIdx.z;
    const int m0 = blockIdx.y * 64;
    const int n0 = blockIdx.x * 128;

    const __nv_bfloat16* pAh = Ph + (size_t)b * L * L;
    const __nv_bfloat16* pAl = Pl + (size_t)b * L * L;
    const __nv_bfloat16* pBh = Bh + (size_t)b * D * L;
    const __nv_bfloat16* pBl = Bl + (size_t)b * D * L;

    const int rowbase = (wid & 1) * 32;
    const int colbase = (wid >> 1) * 32;
    const int lrow = lid & 15;
    const uint32_t lkoff = (uint32_t)((lid >> 4) * 16);

    float acc[2][4][4];
    #pragma unroll
    for (int mt = 0; mt < 2; mt++)
        #pragma unroll
        for (int nt = 0; nt < 4; nt++)
            #pragma unroll
            for (int r = 0; r < 4; r++) acc[mt][nt][r] = 0.0f;

    const int nch = L >> 6;   // 16

    pv_issue_stage(pAh, pAl, pBh, pBl, m0, n0, 0, sb, tid);

    for (int c = 0; c < nch; c++) {
        if (c + 1 < nch) {
            pv_issue_stage(pAh, pAl, pBh, pBl, m0, n0, (c + 1) << 6,
                           sb + (uint32_t)((c + 1) & 1) * PV_STAGE, tid);
            CP_ASYNC_WAIT(1);
        } else {
            CP_ASYNC_WAIT(0);
        }
        __syncthreads();

        const uint32_t st = sb + (uint32_t)(c & 1) * PV_STAGE;
        const uint32_t aH = st + PV_AH;
        const uint32_t aL = st + PV_AL;
        const uint32_t bH = st + PV_BH;
        const uint32_t bL = st + PV_BL;

        #pragma unroll
        for (int ks = 0; ks < 4; ks++) {
            const uint32_t kb = (uint32_t)(ks * 32) + lkoff;
            uint32_t ah[2][4], al[2][4];
            #pragma unroll
            for (int mt = 0; mt < 2; mt++) {
                const uint32_t boff = (uint32_t)((rowbase + mt * 16 + lrow) * 128) + kb;
                ldsm_x4(ah[mt][0], ah[mt][1], ah[mt][2], ah[mt][3], aH + SWZ(boff));
                ldsm_x4(al[mt][0], al[mt][1], al[mt][2], al[mt][3], aL + SWZ(boff));
            }
            #pragma unroll
            for (int np = 0; np < 2; np++) {
                const uint32_t boff = (uint32_t)((colbase + np * 16 + lrow) * 128) + kb;
                uint32_t bh[4], bl[4];
                ldsm_x4(bh[0], bh[1], bh[2], bh[3], bH + SWZ(boff));
                ldsm_x4(bl[0], bl[1], bl[2], bl[3], bL + SWZ(boff));
                #pragma unroll
                for (int mt = 0; mt < 2; mt++) {
                    float* c0 = acc[mt][np * 2 + 0];
                    float* c1 = acc[mt][np * 2 + 1];
                    mma_bf16(c0[0], c0[1], c0[2], c0[3],
                             ah[mt][0], ah[mt][1], ah[mt][2], ah[mt][3], bh[0], bh[2]);
                    mma_bf16(c1[0], c1[1], c1[2], c1[3],
                             ah[mt][0], ah[mt][1], ah[mt][2], ah[mt][3], bh[1], bh[3]);
                    mma_bf16(c0[0], c0[1], c0[2], c0[3],
                             ah[mt][0], ah[mt][1], ah[mt][2], ah[mt][3], bl[0], bl[2]);
                    mma_bf16(c1[0], c1[1], c1[2], c1[3],
                             ah[mt][0], ah[mt][1], ah[mt][2], ah[mt][3], bl[1], bl[3]);
                    mma_bf16(c0[0], c0[1], c0[2], c0[3],
                             al[mt][0], al[mt][1], al[mt][2], al[mt][3], bh[0], bh[2]);
                    mma_bf16(c1[0], c1[1], c1[2], c1[3],
                             al[mt][0], al[mt][1], al[mt][2], al[mt][3], bh[1], bh[3]);
                }
            }
        }
        __syncthreads();
    }

    float* pO = O + (size_t)b * L * D;
    const int trow = lid >> 2;
    const int tcol = (lid & 3) * 2;
    #pragma unroll
    for (int mt = 0; mt < 2; mt++) {
        #pragma unroll
        for (int nt = 0; nt < 4; nt++) {
            const int row = m0 + rowbase + mt * 16 + trow;
            const int col = n0 + colbase + nt * 8 + tcol;
            *(float2*)(pO + (size_t)row * D + col) =
                make_float2(acc[mt][nt][0], acc[mt][nt][1]);
            *(float2*)(pO + (size_t)(row + 8) * D + col) =
                make_float2(acc[mt][nt][2], acc[mt][nt][3]);
        }
    }
}

// ---------------------------------------------------------------------------
// softmax in-place; emits P hi/lo bf16.
// ---------------------------------------------------------------------------
__global__ void __launch_bounds__(256) softmax_kernel(float* __restrict__ attn) {
    const size_t row = blockIdx.x;
    float* p = attn + row * L;
    __nv_bfloat16* ph = g_ph + row * L;
    __nv_bfloat16* pl = g_pl + row * L;
    const int tid = threadIdx.x;

    float4 v = ((const float4*)p)[tid];
    float m = fmaxf(fmaxf(v.x, v.y), fmaxf(v.z, v.w));
    #pragma unroll
    for (int o = 16; o > 0; o >>= 1) m = fmaxf(m, __shfl_xor_sync(0xffffffffu, m, o));

    __shared__ float smem[8];
    __shared__ float stat;
    const int wid = tid >> 5, lid = tid & 31;
    if (lid == 0) smem[wid] = m;
    __syncthreads();
    if (tid == 0) {
        float mm = smem[0];
        #pragma unroll
        for (int i = 1; i < 8; i++) mm = fmaxf(mm, smem[i]);
        stat = mm;
    }
    __syncthreads();
    const float rmax = stat;

    if (rmax == neg_inf()) {
        ((float4*)p)[tid] = make_float4(0.f, 0.f, 0.f, 0.f);
        const uint2 z = make_uint2(0u, 0u);
        ((uint2*)ph)[tid] = z;
        ((uint2*)pl)[tid] = z;
        return;
    }

    float4 e;
    e.x = __expf(v.x - rmax); e.y = __expf(v.y - rmax);
    e.z = __expf(v.z - rmax); e.w = __expf(v.w - rmax);
    float s = (e.x + e.y) + (e.z + e.w);
    #pragma unroll
    for (int o = 16; o > 0; o >>= 1) s += __shfl_xor_sync(0xffffffffu, s, o);
    if (lid == 0) smem[wid] = s;
    __syncthreads();
    if (tid == 0) {
        float ss = smem[0];
        #pragma unroll
        for (int i = 1; i < 8; i++) ss += smem[i];
        stat = 1.0f / ss;
    }
    __syncthreads();
    const float inv = stat;
    e.x *= inv; e.y *= inv; e.z *= inv; e.w *= inv;
    ((float4*)p)[tid] = e;

    __nv_bfloat16 h0 = __float2bfloat16(e.x), h1 = __float2bfloat16(e.y);
    __nv_bfloat16 h2 = __float2bfloat16(e.z), h3 = __float2bfloat16(e.w);
    __nv_bfloat16 l0 = __float2bfloat16(e.x - __bfloat162float(h0));
    __nv_bfloat16 l1 = __float2bfloat16(e.y - __bfloat162float(h1));
    __nv_bfloat16 l2 = __float2bfloat16(e.z - __bfloat162float(h2));
    __nv_bfloat16 l3 = __float2bfloat16(e.w - __bfloat162float(h3));
    __nv_bfloat162 hp0, hp1, lp0, lp1;
    hp0.x = h0; hp0.y = h1; hp1.x = h2; hp1.y = h3;
    lp0.x = l0; lp0.y = l1; lp1.x = l2; lp1.y = l3;
    ((__nv_bfloat162*)ph)[tid * 2]     = hp0;
    ((__nv_bfloat162*)ph)[tid * 2 + 1] = hp1;
    ((__nv_bfloat162*)pl)[tid * 2]     = lp0;
    ((__nv_bfloat162*)pl)[tid * 2 + 1] = lp1;
}

// ---------------------------------------------------------------------------
// Launch
// ---------------------------------------------------------------------------
extern "C" void kernel_launch(void* const* d_in, const int* in_sizes, int n_in,
                              void* d_out, int out_size) {
    const float* q = (const float*)d_in[0];
    float* out  = (float*)d_out;
    float* attn = (float*)d_out + (size_t)B * L * D;

    void *qh, *ql, *qth, *qtl, *ph, *pl;
    cudaGetSymbolAddress(&qh,  g_qh);
    cudaGetSymbolAddress(&ql,  g_ql);
    cudaGetSymbolAddress(&qth, g_qth);
    cudaGetSymbolAddress(&qtl, g_qtl);
    cudaGetSymbolAddress(&ph,  g_ph);
    cudaGetSymbolAddress(&pl,  g_pl);

    cudaFuncSetAttribute(gemm_qqt_sym_kernel, cudaFuncAttributeMaxDynamicSharedMemorySize, GEMM1_SMEM);
    cudaFuncSetAttribute(gemm_pv_kernel,      cudaFuncAttributeMaxDynamicSharedMemorySize, PV_SMEM);

    dim3 gs(D / 32, L / 32, B);
    split_q_kernel<<<gs, dim3(32, 8)>>>(q);

    dim3 g1(36, 1, B);
    gemm_qqt_sym_kernel<<<g1, 512, GEMM1_SMEM>>>(
        (const __nv_bfloat16*)qh, (const __nv_bfloat16*)ql, attn);

    softmax_kernel<<<B * L, 256>>>(attn);

    dim3 g2(D / 128, L / 64, B);
    gemm_pv_kernel<<<g2, 256, PV_SMEM>>>(
        (const __nv_bfloat16*)ph, (const __nv_bfloat16*)pl,
        (const __nv_bfloat16*)qth, (const __nv_bfloat16*)qtl, out);
}

// round 10
// speedup vs baseline: 1.0188x; 1.0188x over previous
#include <cuda_runtime.h>
#include <cuda_bf16.h>
#include <cstdint>

#define B   32
#define L   1024
#define D   256
#define INV_TEMP (1.0f/16.0f)

// ---------------------------------------------------------------------------
// Scratch
// ---------------------------------------------------------------------------
__device__ __nv_bfloat16 g_qh [B * L * D];
__device__ __nv_bfloat16 g_ql [B * L * D];
__device__ __nv_bfloat16 g_qth[B * D * L];
__device__ __nv_bfloat16 g_qtl[B * D * L];
__device__ __nv_bfloat16 g_ph [B * L * L];
__device__ __nv_bfloat16 g_pl [B * L * L];

// symmetric tile decode: 128-row block i, 64-col block j64, j64 >= 2i (72 tiles)
__constant__ uint8_t c_ti[72] = {
    0,0,0,0,0,0,0,0,0,0,0,0,0,0,0,0,
    1,1,1,1,1,1,1,1,1,1,1,1,1,1,
    2,2,2,2,2,2,2,2,2,2,2,2,
    3,3,3,3,3,3,3,3,3,3,
    4,4,4,4,4,4,4,4,
    5,5,5,5,5,5,
    6,6,6,6,
    7,7};
__constant__ uint8_t c_tj[72] = {
    0,1,2,3,4,5,6,7,8,9,10,11,12,13,14,15,
    2,3,4,5,6,7,8,9,10,11,12,13,14,15,
    4,5,6,7,8,9,10,11,12,13,14,15,
    6,7,8,9,10,11,12,13,14,15,
    8,9,10,11,12,13,14,15,
    10,11,12,13,14,15,
    12,13,14,15,
    14,15};

__device__ __forceinline__ float neg_inf() { return __int_as_float(0xff800000); }

__device__ __forceinline__ uint32_t smem_to_u32(const void* p) {
    uint32_t a;
    asm("{ .reg .u64 t; cvta.to.shared.u64 t, %1; cvt.u32.u64 %0, t; }" : "=r"(a) : "l"(p));
    return a;
}

#define SWZ(x) ((x) ^ (((x) >> 3) & 0x70))

__device__ __forceinline__ void ldsm_x4(uint32_t& r0, uint32_t& r1, uint32_t& r2, uint32_t& r3,
                                        uint32_t addr) {
    asm volatile("ldmatrix.sync.aligned.m8n8.x4.shared.b16 {%0,%1,%2,%3}, [%4];"
                 : "=r"(r0), "=r"(r1), "=r"(r2), "=r"(r3) : "r"(addr));
}

__device__ __forceinline__ void mma_bf16(float& c0, float& c1, float& c2, float& c3,
                                         uint32_t a0, uint32_t a1, uint32_t a2, uint32_t a3,
                                         uint32_t b0, uint32_t b1) {
    asm volatile("mma.sync.aligned.m16n8k16.row.col.f32.bf16.bf16.f32 "
                 "{%0,%1,%2,%3}, {%4,%5,%6,%7}, {%8,%9}, {%0,%1,%2,%3};"
                 : "+f"(c0), "+f"(c1), "+f"(c2), "+f"(c3)
                 : "r"(a0), "r"(a1), "r"(a2), "r"(a3), "r"(b0), "r"(b1));
}

#define CP_ASYNC_16(dst, src) \
    asm volatile("cp.async.cg.shared.global [%0], [%1], 16;" :: "r"(dst), "l"(src))
#define CP_ASYNC_COMMIT() asm volatile("cp.async.commit_group;" ::: "memory")
#define CP_ASYNC_WAIT(n)  asm volatile("cp.async.wait_group %0;" :: "n"(n) : "memory")

// ---------------------------------------------------------------------------
// Kernel A: split q -> bf16 hi/lo + transposed hi/lo copies.
// ---------------------------------------------------------------------------
__global__ void __launch_bounds__(256) split_q_kernel(const float* __restrict__ q) {
    const int b  = blockIdx.z;
    const int d0 = blockIdx.x * 32;
    const int l0 = blockIdx.y * 32;
    const float* Q = q + (size_t)b * L * D;
    __shared__ float t[32][33];
    const int tx = threadIdx.x, ty = threadIdx.y;

    #pragma unroll
    for (int i = 0; i < 4; i++) {
        const int r = ty + i * 8;
        const float v = Q[(size_t)(l0 + r) * D + d0 + tx];
        t[r][tx] = v;
        __nv_bfloat16 h  = __float2bfloat16(v);
        __nv_bfloat16 lo = __float2bfloat16(v - __bfloat162float(h));
        const size_t idx = (size_t)b * L * D + (size_t)(l0 + r) * D + d0 + tx;
        g_qh[idx] = h;
        g_ql[idx] = lo;
    }
    __syncthreads();
    #pragma unroll
    for (int i = 0; i < 4; i++) {
        const int r = ty + i * 8;
        const float v = t[tx][r];
        __nv_bfloat16 h  = __float2bfloat16(v);
        __nv_bfloat16 lo = __float2bfloat16(v - __bfloat162float(h));
        const size_t idx = (size_t)b * D * L + (size_t)(d0 + r) * L + l0 + tx;
        g_qth[idx] = h;
        g_qtl[idx] = lo;
    }
}

// ---------------------------------------------------------------------------
// Generic tile loader: ROWS x 64 bf16, 128B swizzled rows, NT threads.
// ---------------------------------------------------------------------------
template <int ROWS, int NT>
__device__ __forceinline__ void issue_tile(const __nv_bfloat16* __restrict__ src,
                                           int row0, int ld, int k0,
                                           uint32_t smem_tile, int tid) {
    #pragma unroll
    for (int i = 0; i < (ROWS * 8) / NT; i++) {
        const int chunk = tid + i * NT;
        const int row = chunk >> 3;
        const int c16 = chunk & 7;
        const __nv_bfloat16* g = src + (size_t)(row0 + row) * ld + k0 + c16 * 8;
        CP_ASYNC_16(smem_tile + SWZ((uint32_t)(row * 128 + c16 * 16)), g);
    }
}

// ===========================================================================
// GEMM1 (symmetric): S = Q@Q^T. CTA tile 128x64, 256 thr, 8 warps (4x2),
// warp tile 32x32, 2-stage. stage = A 32KB + B 16KB = 48KB; 96KB -> 2 CTAs/SM.
// grid (72, 1, B); direct write + mirror write for fully off-diagonal tiles.
// ===========================================================================
#define G1_TA 16384                      // 128 x 128B (per hi or lo)
#define G1_TB 8192                       // 64 x 128B
#define G1_STAGE (2 * G1_TA + 2 * G1_TB) // 48KB
#define G1_SMEM (2 * G1_STAGE)           // 96KB
#define G1_AH 0
#define G1_AL G1_TA
#define G1_BH (2 * G1_TA)
#define G1_BL (2 * G1_TA + G1_TB)

__device__ __forceinline__ void g1_issue_stage(
        const __nv_bfloat16* pQh, const __nv_bfloat16* pQl,
        int m0, int n0, int k0, uint32_t st, int tid) {
    issue_tile<128, 256>(pQh, m0, D, k0, st + G1_AH, tid);
    issue_tile<128, 256>(pQl, m0, D, k0, st + G1_AL, tid);
    issue_tile<64, 256>(pQh, n0, D, k0, st + G1_BH, tid);
    issue_tile<64, 256>(pQl, n0, D, k0, st + G1_BL, tid);
    CP_ASYNC_COMMIT();
}

__global__ void __launch_bounds__(256, 2)
gemm_qqt_sym_kernel(const __nv_bfloat16* __restrict__ Qh, const __nv_bfloat16* __restrict__ Ql,
                    float* __restrict__ S) {
    extern __shared__ char smem[];
    const uint32_t sb = smem_to_u32(smem);
    const int tid = threadIdx.x, wid = tid >> 5, lid = tid & 31;
    const int b   = blockIdx.z;
    const int bi  = c_ti[blockIdx.x];
    const int bj64 = c_tj[blockIdx.x];
    const int m0 = bi * 128;
    const int n0 = bj64 * 64;

    const __nv_bfloat16* pQh = Qh + (size_t)b * L * D;
    const __nv_bfloat16* pQl = Ql + (size_t)b * L * D;

    const int rowbase = (wid & 3) * 32;     // 4x2 warp grid, warp tile 32x32
    const int colbase = (wid >> 2) * 32;
    const int lrow = lid & 15;
    const uint32_t lkoff = (uint32_t)((lid >> 4) * 16);

    float acc[2][4][4];
    #pragma unroll
    for (int mt = 0; mt < 2; mt++)
        #pragma unroll
        for (int nt = 0; nt < 4; nt++)
            #pragma unroll
            for (int r = 0; r < 4; r++) acc[mt][nt][r] = 0.0f;

    const int nch = D >> 6;   // 4
    g1_issue_stage(pQh, pQl, m0, n0, 0, sb, tid);

    for (int c = 0; c < nch; c++) {
        if (c + 1 < nch) {
            g1_issue_stage(pQh, pQl, m0, n0, (c + 1) << 6,
                           sb + (uint32_t)((c + 1) & 1) * G1_STAGE, tid);
            CP_ASYNC_WAIT(1);
        } else {
            CP_ASYNC_WAIT(0);
        }
        __syncthreads();

        const uint32_t st = sb + (uint32_t)(c & 1) * G1_STAGE;
        const uint32_t aH = st + G1_AH;
        const uint32_t aL = st + G1_AL;
        const uint32_t bH = st + G1_BH;
        const uint32_t bL = st + G1_BL;

        #pragma unroll
        for (int ks = 0; ks < 4; ks++) {
            const uint32_t kb = (uint32_t)(ks * 32) + lkoff;
            uint32_t ah[2][4], al[2][4];
            #pragma unroll
            for (int mt = 0; mt < 2; mt++) {
                const uint32_t boff = (uint32_t)((rowbase + mt * 16 + lrow) * 128) + kb;
                ldsm_x4(ah[mt][0], ah[mt][1], ah[mt][2], ah[mt][3], aH + SWZ(boff));
                ldsm_x4(al[mt][0], al[mt][1], al[mt][2], al[mt][3], aL + SWZ(boff));
            }
            #pragma unroll
            for (int np = 0; np < 2; np++) {
                const uint32_t boff = (uint32_t)((colbase + np * 16 + lrow) * 128) + kb;
                uint32_t bh[4], bl[4];
                ldsm_x4(bh[0], bh[1], bh[2], bh[3], bH + SWZ(boff));
                ldsm_x4(bl[0], bl[1], bl[2], bl[3], bL + SWZ(boff));
                #pragma unroll
                for (int mt = 0; mt < 2; mt++) {
                    float* c0 = acc[mt][np * 2 + 0];
                    float* c1 = acc[mt][np * 2 + 1];
                    mma_bf16(c0[0], c0[1], c0[2], c0[3],
                             ah[mt][0], ah[mt][1], ah[mt][2], ah[mt][3], bh[0], bh[2]);
                    mma_bf16(c1[0], c1[1], c1[2], c1[3],
                             ah[mt][0], ah[mt][1], ah[mt][2], ah[mt][3], bh[1], bh[3]);
                    mma_bf16(c0[0], c0[1], c0[2], c0[3],
                             ah[mt][0], ah[mt][1], ah[mt][2], ah[mt][3], bl[0], bl[2]);
                    mma_bf16(c1[0], c1[1], c1[2], c1[3],
                             ah[mt][0], ah[mt][1], ah[mt][2], ah[mt][3], bl[1], bl[3]);
                    mma_bf16(c0[0], c0[1], c0[2], c0[3],
                             al[mt][0], al[mt][1], al[mt][2], al[mt][3], bh[0], bh[2]);
                    mma_bf16(c1[0], c1[1], c1[2], c1[3],
                             al[mt][0], al[mt][1], al[mt][2], al[mt][3], bh[1], bh[3]);
                }
            }
        }
        __syncthreads();
    }

    // mask + scale
    #pragma unroll
    for (int mt = 0; mt < 2; mt++)
        #pragma unroll
        for (int nt = 0; nt < 4; nt++)
            #pragma unroll
            for (int r = 0; r < 4; r++) {
                float v = acc[mt][nt][r];
                acc[mt][nt][r] = (v == 0.0f) ? neg_inf() : v * INV_TEMP;
            }

    float* pS = S + (size_t)b * L * L;
    const int trow = lid >> 2;
    const int tcol = (lid & 3) * 2;

    // direct write: rows [m0,m0+128), cols [n0,n0+64)
    #pragma unroll
    for (int mt = 0; mt < 2; mt++) {
        #pragma unroll
        for (int nt = 0; nt < 4; nt++) {
            const int row = m0 + rowbase + mt * 16 + trow;
            const int col = n0 + colbase + nt * 8 + tcol;
            *(float2*)(pS + (size_t)row * L + col) =
                make_float2(acc[mt][nt][0], acc[mt][nt][1]);
            *(float2*)(pS + (size_t)(row + 8) * L + col) =
                make_float2(acc[mt][nt][2], acc[mt][nt][3]);
        }
    }

    if ((bj64 >> 1) > bi) {
        // mirror write: stage transpose in smem (64 x 132 floats)
        float* smemT = (float*)smem;
        #pragma unroll
        for (int mt = 0; mt < 2; mt++) {
            #pragma unroll
            for (int nt = 0; nt < 4; nt++) {
                const int i0 = rowbase + mt * 16 + trow;   // 0..127
                const int j0 = colbase + nt * 8 + tcol;    // 0..63
                smemT[(j0 + 0) * 132 + i0]     = acc[mt][nt][0];
                smemT[(j0 + 1) * 132 + i0]     = acc[mt][nt][1];
                smemT[(j0 + 0) * 132 + i0 + 8] = acc[mt][nt][2];
                smemT[(j0 + 1) * 132 + i0 + 8] = acc[mt][nt][3];
            }
        }
        __syncthreads();
        // write rows [n0,n0+64), cols [m0,m0+128)
        const int j       = tid >> 2;            // 0..63
        const int quarter = (tid & 3) * 32;      // 0,32,64,96
        float* dst = pS + (size_t)(n0 + j) * L + m0 + quarter;
        const float* srcrow = smemT + j * 132 + quarter;
        #pragma unroll
        for (int u = 0; u < 8; u++) {
            *(float4*)(dst + u * 4) = *(const float4*)(srcrow + u * 4);
        }
    }
}

// ===========================================================================
// GEMM2: O = P @ Q. CTA tile 64x64, 256 thr, 8 warps (2x4), warp tile 32x16,
// 2-stage. stage = A 16KB + B 16KB = 32KB; 64KB -> 3 CTAs/SM.
// grid (D/64, L/64, B) = (4, 16, 32)
// ===========================================================================
#define PV_TA 8192
#define PV_TB 8192
#define PV_STAGE (2 * PV_TA + 2 * PV_TB)   // 32KB
#define PV_SMEM (2 * PV_STAGE)             // 64KB
#define PV_AH 0
#define PV_AL PV_TA
#define PV_BH (2 * PV_TA)
#define PV_BL (2 * PV_TA + PV_TB)

__device__ __forceinline__ void pv_issue_stage(
        const __nv_bfloat16* pAh, const __nv_bfloat16* pAl,
        const __nv_bfloat16* pBh, const __nv_bfloat16* pBl,
        int m0, int n0, int k0, uint32_t st, int tid) {
    issue_tile<64, 256>(pAh, m0, L, k0, st + PV_AH, tid);
    issue_tile<64, 256>(pAl, m0, L, k0, st + PV_AL, tid);
    issue_tile<64, 256>(pBh, n0, L, k0, st + PV_BH, tid);
    issue_tile<64, 256>(pBl, n0, L, k0, st + PV_BL, tid);
    CP_ASYNC_COMMIT();
}

__global__ void __launch_bounds__(256, 3)
gemm_pv_kernel(const __nv_bfloat16* __restrict__ Ph, const __nv_bfloat16* __restrict__ Pl,
               const __nv_bfloat16* __restrict__ Bh, const __nv_bfloat16* __restrict__ Bl,
               float* __restrict__ O) {
    extern __shared__ char smem[];
    const uint32_t sb = smem_to_u32(smem);
    const int tid = threadIdx.x, wid = tid >> 5, lid = tid & 31;
    const int b  = blockIdx.z;
    const int m0 = blockIdx.y * 64;
    const int n0 = blockIdx.x * 64;

    const __nv_bfloat16* pAh = Ph + (size_t)b * L * L;
    const __nv_bfloat16* pAl = Pl + (size_t)b * L * L;
    const __nv_bfloat16* pBh = Bh + (size_t)b * D * L;
    const __nv_bfloat16* pBl = Bl + (size_t)b * D * L;

    const int rowbase = (wid & 1) * 32;      // 2 row groups of 32
    const int colbase = (wid >> 1) * 16;     // 4 col groups of 16
    const int lrow = lid & 15;
    const uint32_t lkoff = (uint32_t)((lid >> 4) * 16);

    float acc[2][2][4];
    #pragma unroll
    for (int mt = 0; mt < 2; mt++)
        #pragma unroll
        for (int nt = 0; nt < 2; nt++)
            #pragma unroll
            for (int r = 0; r < 4; r++) acc[mt][nt][r] = 0.0f;

    const int nch = L >> 6;   // 16

    pv_issue_stage(pAh, pAl, pBh, pBl, m0, n0, 0, sb, tid);

    for (int c = 0; c < nch; c++) {
        if (c + 1 < nch) {
            pv_issue_stage(pAh, pAl, pBh, pBl, m0, n0, (c + 1) << 6,
                           sb + (uint32_t)((c + 1) & 1) * PV_STAGE, tid);
            CP_ASYNC_WAIT(1);
        } else {
            CP_ASYNC_WAIT(0);
        }
        __syncthreads();

        const uint32_t st = sb + (uint32_t)(c & 1) * PV_STAGE;
        const uint32_t aH = st + PV_AH;
        const uint32_t aL = st + PV_AL;
        const uint32_t bH = st + PV_BH;
        const uint32_t bL = st + PV_BL;

        #pragma unroll
        for (int ks = 0; ks < 4; ks++) {
            const uint32_t kb = (uint32_t)(ks * 32) + lkoff;
            uint32_t ah[2][4], al[2][4];
            #pragma unroll
            for (int mt = 0; mt < 2; mt++) {
                const uint32_t boff = (uint32_t)((rowbase + mt * 16 + lrow) * 128) + kb;
                ldsm_x4(ah[mt][0], ah[mt][1], ah[mt][2], ah[mt][3], aH + SWZ(boff));
                ldsm_x4(al[mt][0], al[mt][1], al[mt][2], al[mt][3], aL + SWZ(boff));
            }
            const uint32_t boff = (uint32_t)((colbase + lrow) * 128) + kb;
            uint32_t bh[4], bl[4];
            ldsm_x4(bh[0], bh[1], bh[2], bh[3], bH + SWZ(boff));
            ldsm_x4(bl[0], bl[1], bl[2], bl[3], bL + SWZ(boff));
            #pragma unroll
            for (int mt = 0; mt < 2; mt++) {
                float* c0 = acc[mt][0];
                float* c1 = acc[mt][1];
                mma_bf16(c0[0], c0[1], c0[2], c0[3],
                         ah[mt][0], ah[mt][1], ah[mt][2], ah[mt][3], bh[0], bh[2]);
                mma_bf16(c1[0], c1[1], c1[2], c1[3],
                         ah[mt][0], ah[mt][1], ah[mt][2], ah[mt][3], bh[1], bh[3]);
                mma_bf16(c0[0], c0[1], c0[2], c0[3],
                         ah[mt][0], ah[mt][1], ah[mt][2], ah[mt][3], bl[0], bl[2]);
                mma_bf16(c1[0], c1[1], c1[2], c1[3],
                         ah[mt][0], ah[mt][1], ah[mt][2], ah[mt][3], bl[1], bl[3]);
                mma_bf16(c0[0], c0[1], c0[2], c0[3],
                         al[mt][0], al[mt][1], al[mt][2], al[mt][3], bh[0], bh[2]);
                mma_bf16(c1[0], c1[1], c1[2], c1[3],
                         al[mt][0], al[mt][1], al[mt][2], al[mt][3], bh[1], bh[3]);
            }
        }
        __syncthreads();
    }

    float* pO = O + (size_t)b * L * D;
    const int trow = lid >> 2;
    const int tcol = (lid & 3) * 2;
    #pragma unroll
    for (int mt = 0; mt < 2; mt++) {
        #pragma unroll
        for (int nt = 0; nt < 2; nt++) {
            const int row = m0 + rowbase + mt * 16 + trow;
            const int col = n0 + colbase + nt * 8 + tcol;
            *(float2*)(pO + (size_t)row * D + col) =
                make_float2(acc[mt][nt][0], acc[mt][nt][1]);
            *(float2*)(pO + (size_t)(row + 8) * D + col) =
                make_float2(acc[mt][nt][2], acc[mt][nt][3]);
        }
    }
}

// ---------------------------------------------------------------------------
// softmax in-place; emits P hi/lo bf16.
// ---------------------------------------------------------------------------
__global__ void __launch_bounds__(256) softmax_kernel(float* __restrict__ attn) {
    const size_t row = blockIdx.x;
    float* p = attn + row * L;
    __nv_bfloat16* ph = g_ph + row * L;
    __nv_bfloat16* pl = g_pl + row * L;
    const int tid = threadIdx.x;

    float4 v = ((const float4*)p)[tid];
    float m = fmaxf(fmaxf(v.x, v.y), fmaxf(v.z, v.w));
    #pragma unroll
    for (int o = 16; o > 0; o >>= 1) m = fmaxf(m, __shfl_xor_sync(0xffffffffu, m, o));

    __shared__ float smem[8];
    __shared__ float stat;
    const int wid = tid >> 5, lid = tid & 31;
    if (lid == 0) smem[wid] = m;
    __syncthreads();
    if (tid == 0) {
        float mm = smem[0];
        #pragma unroll
        for (int i = 1; i < 8; i++) mm = fmaxf(mm, smem[i]);
        stat = mm;
    }
    __syncthreads();
    const float rmax = stat;

    if (rmax == neg_inf()) {
        ((float4*)p)[tid] = make_float4(0.f, 0.f, 0.f, 0.f);
        const uint2 z = make_uint2(0u, 0u);
        ((uint2*)ph)[tid] = z;
        ((uint2*)pl)[tid] = z;
        return;
    }

    float4 e;
    e.x = __expf(v.x - rmax); e.y = __expf(v.y - rmax);
    e.z = __expf(v.z - rmax); e.w = __expf(v.w - rmax);
    float s = (e.x + e.y) + (e.z + e.w);
    #pragma unroll
    for (int o = 16; o > 0; o >>= 1) s += __shfl_xor_sync(0xffffffffu, s, o);
    if (lid == 0) smem[wid] = s;
    __syncthreads();
    if (tid == 0) {
        float ss = smem[0];
        #pragma unroll
        for (int i = 1; i < 8; i++) ss += smem[i];
        stat = 1.0f / ss;
    }
    __syncthreads();
    const float inv = stat;
    e.x *= inv; e.y *= inv; e.z *= inv; e.w *= inv;
    ((float4*)p)[tid] = e;

    __nv_bfloat16 h0 = __float2bfloat16(e.x), h1 = __float2bfloat16(e.y);
    __nv_bfloat16 h2 = __float2bfloat16(e.z), h3 = __float2bfloat16(e.w);
    __nv_bfloat16 l0 = __float2bfloat16(e.x - __bfloat162float(h0));
    __nv_bfloat16 l1 = __float2bfloat16(e.y - __bfloat162float(h1));
    __nv_bfloat16 l2 = __float2bfloat16(e.z - __bfloat162float(h2));
    __nv_bfloat16 l3 = __float2bfloat16(e.w - __bfloat162float(h3));
    __nv_bfloat162 hp0, hp1, lp0, lp1;
    hp0.x = h0; hp0.y = h1; hp1.x = h2; hp1.y = h3;
    lp0.x = l0; lp0.y = l1; lp1.x = l2; lp1.y = l3;
    ((__nv_bfloat162*)ph)[tid * 2]     = hp0;
    ((__nv_bfloat162*)ph)[tid * 2 + 1] = hp1;
    ((__nv_bfloat162*)pl)[tid * 2]     = lp0;
    ((__nv_bfloat162*)pl)[tid * 2 + 1] = lp1;
}

// ---------------------------------------------------------------------------
// Launch
// ---------------------------------------------------------------------------
extern "C" void kernel_launch(void* const* d_in, const int* in_sizes, int n_in,
                              void* d_out, int out_size) {
    const float* q = (const float*)d_in[0];
    float* out  = (float*)d_out;
    float* attn = (float*)d_out + (size_t)B * L * D;

    void *qh, *ql, *qth, *qtl, *ph, *pl;
    cudaGetSymbolAddress(&qh,  g_qh);
    cudaGetSymbolAddress(&ql,  g_ql);
    cudaGetSymbolAddress(&qth, g_qth);
    cudaGetSymbolAddress(&qtl, g_qtl);
    cudaGetSymbolAddress(&ph,  g_ph);
    cudaGetSymbolAddress(&pl,  g_pl);

    cudaFuncSetAttribute(gemm_qqt_sym_kernel, cudaFuncAttributeMaxDynamicSharedMemorySize, G1_SMEM);
    cudaFuncSetAttribute(gemm_pv_kernel,      cudaFuncAttributeMaxDynamicSharedMemorySize, PV_SMEM);

    dim3 gs(D / 32, L / 32, B);
    split_q_kernel<<<gs, dim3(32, 8)>>>(q);

    dim3 g1(72, 1, B);
    gemm_qqt_sym_kernel<<<g1, 256, G1_SMEM>>>(
        (const __nv_bfloat16*)qh, (const __nv_bfloat16*)ql, attn);

    softmax_kernel<<<B * L, 256>>>(attn);

    dim3 g2(D / 64, L / 64, B);   // (4, 16, 32)
    gemm_pv_kernel<<<g2, 256, PV_SMEM>>>(
        (const __nv_bfloat16*)ph, (const __nv_bfloat16*)pl,
        (const __nv_bfloat16*)qth, (const __nv_bfloat16*)qtl, out);
}

// round 11
// speedup vs baseline: 1.0499x; 1.0306x over previous
#include <cuda_runtime.h>
#include <cuda_bf16.h>
#include <cstdint>

#define B   32
#define L   1024
#define D   256
#define INV_TEMP (1.0f/16.0f)

// ---------------------------------------------------------------------------
// Scratch
// ---------------------------------------------------------------------------
__device__ __nv_bfloat16 g_qh [B * L * D];
__device__ __nv_bfloat16 g_ql [B * L * D];
__device__ __nv_bfloat16 g_qth[B * D * L];
__device__ __nv_bfloat16 g_qtl[B * D * L];
__device__ __nv_bfloat16 g_ph [B * L * L];
__device__ __nv_bfloat16 g_pl [B * L * L];

// symmetric tile decode: 128-row block i, 64-col block j64, j64 >= 2i (72 tiles)
__constant__ uint8_t c_ti[72] = {
    0,0,0,0,0,0,0,0,0,0,0,0,0,0,0,0,
    1,1,1,1,1,1,1,1,1,1,1,1,1,1,
    2,2,2,2,2,2,2,2,2,2,2,2,
    3,3,3,3,3,3,3,3,3,3,
    4,4,4,4,4,4,4,4,
    5,5,5,5,5,5,
    6,6,6,6,
    7,7};
__constant__ uint8_t c_tj[72] = {
    0,1,2,3,4,5,6,7,8,9,10,11,12,13,14,15,
    2,3,4,5,6,7,8,9,10,11,12,13,14,15,
    4,5,6,7,8,9,10,11,12,13,14,15,
    6,7,8,9,10,11,12,13,14,15,
    8,9,10,11,12,13,14,15,
    10,11,12,13,14,15,
    12,13,14,15,
    14,15};

__device__ __forceinline__ float neg_inf() { return __int_as_float(0xff800000); }

__device__ __forceinline__ uint32_t smem_to_u32(const void* p) {
    uint32_t a;
    asm("{ .reg .u64 t; cvta.to.shared.u64 t, %1; cvt.u32.u64 %0, t; }" : "=r"(a) : "l"(p));
    return a;
}

#define SWZ(x) ((x) ^ (((x) >> 3) & 0x70))

__device__ __forceinline__ void ldsm_x4(uint32_t& r0, uint32_t& r1, uint32_t& r2, uint32_t& r3,
                                        uint32_t addr) {
    asm volatile("ldmatrix.sync.aligned.m8n8.x4.shared.b16 {%0,%1,%2,%3}, [%4];"
                 : "=r"(r0), "=r"(r1), "=r"(r2), "=r"(r3) : "r"(addr));
}

__device__ __forceinline__ void mma_bf16(float& c0, float& c1, float& c2, float& c3,
                                         uint32_t a0, uint32_t a1, uint32_t a2, uint32_t a3,
                                         uint32_t b0, uint32_t b1) {
    asm volatile("mma.sync.aligned.m16n8k16.row.col.f32.bf16.bf16.f32 "
                 "{%0,%1,%2,%3}, {%4,%5,%6,%7}, {%8,%9}, {%0,%1,%2,%3};"
                 : "+f"(c0), "+f"(c1), "+f"(c2), "+f"(c3)
                 : "r"(a0), "r"(a1), "r"(a2), "r"(a3), "r"(b0), "r"(b1));
}

#define CP_ASYNC_16(dst, src) \
    asm volatile("cp.async.cg.shared.global [%0], [%1], 16;" :: "r"(dst), "l"(src))
#define CP_ASYNC_COMMIT() asm volatile("cp.async.commit_group;" ::: "memory")
#define CP_ASYNC_WAIT(n)  asm volatile("cp.async.wait_group %0;" :: "n"(n) : "memory")

// ---------------------------------------------------------------------------
// Kernel A: split q -> bf16 hi/lo + transposed hi/lo copies.
// ---------------------------------------------------------------------------
__global__ void __launch_bounds__(256) split_q_kernel(const float* __restrict__ q) {
    const int b  = blockIdx.z;
    const int d0 = blockIdx.x * 32;
    const int l0 = blockIdx.y * 32;
    const float* Q = q + (size_t)b * L * D;
    __shared__ float t[32][33];
    const int tx = threadIdx.x, ty = threadIdx.y;

    #pragma unroll
    for (int i = 0; i < 4; i++) {
        const int r = ty + i * 8;
        const float v = Q[(size_t)(l0 + r) * D + d0 + tx];
        t[r][tx] = v;
        __nv_bfloat16 h  = __float2bfloat16(v);
        __nv_bfloat16 lo = __float2bfloat16(v - __bfloat162float(h));
        const size_t idx = (size_t)b * L * D + (size_t)(l0 + r) * D + d0 + tx;
        g_qh[idx] = h;
        g_ql[idx] = lo;
    }
    __syncthreads();
    #pragma unroll
    for (int i = 0; i < 4; i++) {
        const int r = ty + i * 8;
        const float v = t[tx][r];
        __nv_bfloat16 h  = __float2bfloat16(v);
        __nv_bfloat16 lo = __float2bfloat16(v - __bfloat162float(h));
        const size_t idx = (size_t)b * D * L + (size_t)(d0 + r) * L + l0 + tx;
        g_qth[idx] = h;
        g_qtl[idx] = lo;
    }
}

// ---------------------------------------------------------------------------
// Generic tile loader: ROWS x 64 bf16, 128B swizzled rows, NT threads.
// ---------------------------------------------------------------------------
template <int ROWS, int NT>
__device__ __forceinline__ void issue_tile(const __nv_bfloat16* __restrict__ src,
                                           int row0, int ld, int k0,
                                           uint32_t smem_tile, int tid) {
    #pragma unroll
    for (int i = 0; i < (ROWS * 8) / NT; i++) {
        const int chunk = tid + i * NT;
        const int row = chunk >> 3;
        const int c16 = chunk & 7;
        const __nv_bfloat16* g = src + (size_t)(row0 + row) * ld + k0 + c16 * 8;
        CP_ASYNC_16(smem_tile + SWZ((uint32_t)(row * 128 + c16 * 16)), g);
    }
}

// ===========================================================================
// GEMM1 (symmetric, R10 config): CTA tile 128x64, 2-stage, 96KB -> 2 CTAs/SM.
// ===========================================================================
#define G1_TA 16384
#define G1_TB 8192
#define G1_STAGE (2 * G1_TA + 2 * G1_TB)
#define G1_SMEM (2 * G1_STAGE)
#define G1_AH 0
#define G1_AL G1_TA
#define G1_BH (2 * G1_TA)
#define G1_BL (2 * G1_TA + G1_TB)

__device__ __forceinline__ void g1_issue_stage(
        const __nv_bfloat16* pQh, const __nv_bfloat16* pQl,
        int m0, int n0, int k0, uint32_t st, int tid) {
    issue_tile<128, 256>(pQh, m0, D, k0, st + G1_AH, tid);
    issue_tile<128, 256>(pQl, m0, D, k0, st + G1_AL, tid);
    issue_tile<64, 256>(pQh, n0, D, k0, st + G1_BH, tid);
    issue_tile<64, 256>(pQl, n0, D, k0, st + G1_BL, tid);
    CP_ASYNC_COMMIT();
}

__global__ void __launch_bounds__(256, 2)
gemm_qqt_sym_kernel(const __nv_bfloat16* __restrict__ Qh, const __nv_bfloat16* __restrict__ Ql,
                    float* __restrict__ S) {
    extern __shared__ char smem[];
    const uint32_t sb = smem_to_u32(smem);
    const int tid = threadIdx.x, wid = tid >> 5, lid = tid & 31;
    const int b   = blockIdx.z;
    const int bi  = c_ti[blockIdx.x];
    const int bj64 = c_tj[blockIdx.x];
    const int m0 = bi * 128;
    const int n0 = bj64 * 64;

    const __nv_bfloat16* pQh = Qh + (size_t)b * L * D;
    const __nv_bfloat16* pQl = Ql + (size_t)b * L * D;

    const int rowbase = (wid & 3) * 32;
    const int colbase = (wid >> 2) * 32;
    const int lrow = lid & 15;
    const uint32_t lkoff = (uint32_t)((lid >> 4) * 16);

    float acc[2][4][4];
    #pragma unroll
    for (int mt = 0; mt < 2; mt++)
        #pragma unroll
        for (int nt = 0; nt < 4; nt++)
            #pragma unroll
            for (int r = 0; r < 4; r++) acc[mt][nt][r] = 0.0f;

    const int nch = D >> 6;
    g1_issue_stage(pQh, pQl, m0, n0, 0, sb, tid);

    for (int c = 0; c < nch; c++) {
        if (c + 1 < nch) {
            g1_issue_stage(pQh, pQl, m0, n0, (c + 1) << 6,
                           sb + (uint32_t)((c + 1) & 1) * G1_STAGE, tid);
            CP_ASYNC_WAIT(1);
        } else {
            CP_ASYNC_WAIT(0);
        }
        __syncthreads();

        const uint32_t st = sb + (uint32_t)(c & 1) * G1_STAGE;
        const uint32_t aH = st + G1_AH;
        const uint32_t aL = st + G1_AL;
        const uint32_t bH = st + G1_BH;
        const uint32_t bL = st + G1_BL;

        #pragma unroll
        for (int ks = 0; ks < 4; ks++) {
            const uint32_t kb = (uint32_t)(ks * 32) + lkoff;
            uint32_t ah[2][4], al[2][4];
            #pragma unroll
            for (int mt = 0; mt < 2; mt++) {
                const uint32_t boff = (uint32_t)((rowbase + mt * 16 + lrow) * 128) + kb;
                ldsm_x4(ah[mt][0], ah[mt][1], ah[mt][2], ah[mt][3], aH + SWZ(boff));
                ldsm_x4(al[mt][0], al[mt][1], al[mt][2], al[mt][3], aL + SWZ(boff));
            }
            #pragma unroll
            for (int np = 0; np < 2; np++) {
                const uint32_t boff = (uint32_t)((colbase + np * 16 + lrow) * 128) + kb;
                uint32_t bh[4], bl[4];
                ldsm_x4(bh[0], bh[1], bh[2], bh[3], bH + SWZ(boff));
                ldsm_x4(bl[0], bl[1], bl[2], bl[3], bL + SWZ(boff));
                #pragma unroll
                for (int mt = 0; mt < 2; mt++) {
                    float* c0 = acc[mt][np * 2 + 0];
                    float* c1 = acc[mt][np * 2 + 1];
                    mma_bf16(c0[0], c0[1], c0[2], c0[3],
                             ah[mt][0], ah[mt][1], ah[mt][2], ah[mt][3], bh[0], bh[2]);
                    mma_bf16(c1[0], c1[1], c1[2], c1[3],
                             ah[mt][0], ah[mt][1], ah[mt][2], ah[mt][3], bh[1], bh[3]);
                    mma_bf16(c0[0], c0[1], c0[2], c0[3],
                             ah[mt][0], ah[mt][1], ah[mt][2], ah[mt][3], bl[0], bl[2]);
                    mma_bf16(c1[0], c1[1], c1[2], c1[3],
                             ah[mt][0], ah[mt][1], ah[mt][2], ah[mt][3], bl[1], bl[3]);
                    mma_bf16(c0[0], c0[1], c0[2], c0[3],
                             al[mt][0], al[mt][1], al[mt][2], al[mt][3], bh[0], bh[2]);
                    mma_bf16(c1[0], c1[1], c1[2], c1[3],
                             al[mt][0], al[mt][1], al[mt][2], al[mt][3], bh[1], bh[3]);
                }
            }
        }
        __syncthreads();
    }

    #pragma unroll
    for (int mt = 0; mt < 2; mt++)
        #pragma unroll
        for (int nt = 0; nt < 4; nt++)
            #pragma unroll
            for (int r = 0; r < 4; r++) {
                float v = acc[mt][nt][r];
                acc[mt][nt][r] = (v == 0.0f) ? neg_inf() : v * INV_TEMP;
            }

    float* pS = S + (size_t)b * L * L;
    const int trow = lid >> 2;
    const int tcol = (lid & 3) * 2;

    #pragma unroll
    for (int mt = 0; mt < 2; mt++) {
        #pragma unroll
        for (int nt = 0; nt < 4; nt++) {
            const int row = m0 + rowbase + mt * 16 + trow;
            const int col = n0 + colbase + nt * 8 + tcol;
            *(float2*)(pS + (size_t)row * L + col) =
                make_float2(acc[mt][nt][0], acc[mt][nt][1]);
            *(float2*)(pS + (size_t)(row + 8) * L + col) =
                make_float2(acc[mt][nt][2], acc[mt][nt][3]);
        }
    }

    if ((bj64 >> 1) > bi) {
        float* smemT = (float*)smem;
        #pragma unroll
        for (int mt = 0; mt < 2; mt++) {
            #pragma unroll
            for (int nt = 0; nt < 4; nt++) {
                const int i0 = rowbase + mt * 16 + trow;
                const int j0 = colbase + nt * 8 + tcol;
                smemT[(j0 + 0) * 132 + i0]     = acc[mt][nt][0];
                smemT[(j0 + 1) * 132 + i0]     = acc[mt][nt][1];
                smemT[(j0 + 0) * 132 + i0 + 8] = acc[mt][nt][2];
                smemT[(j0 + 1) * 132 + i0 + 8] = acc[mt][nt][3];
            }
        }
        __syncthreads();
        const int j       = tid >> 2;
        const int quarter = (tid & 3) * 32;
        float* dst = pS + (size_t)(n0 + j) * L + m0 + quarter;
        const float* srcrow = smemT + j * 132 + quarter;
        #pragma unroll
        for (int u = 0; u < 8; u++) {
            *(float4*)(dst + u * 4) = *(const float4*)(srcrow + u * 4);
        }
    }
}

// ===========================================================================
// GEMM2 (R8 config): O = P @ Q. CTA 64x128, 8 warps (2x4), warp tile 32x32,
// 2-stage, 96KB smem -> 2 CTAs/SM. grid (D/128, L/64, B)
// ===========================================================================
#define PV_TA 8192
#define PV_TB 16384
#define PV_STAGE (2 * PV_TA + 2 * PV_TB)
#define PV_SMEM (2 * PV_STAGE)
#define PV_AH 0
#define PV_AL PV_TA
#define PV_BH (2 * PV_TA)
#define PV_BL (2 * PV_TA + PV_TB)

__device__ __forceinline__ void pv_issue_stage(
        const __nv_bfloat16* pAh, const __nv_bfloat16* pAl,
        const __nv_bfloat16* pBh, const __nv_bfloat16* pBl,
        int m0, int n0, int k0, uint32_t st, int tid) {
    issue_tile<64, 256>(pAh, m0, L, k0, st + PV_AH, tid);
    issue_tile<64, 256>(pAl, m0, L, k0, st + PV_AL, tid);
    issue_tile<128, 256>(pBh, n0, L, k0, st + PV_BH, tid);
    issue_tile<128, 256>(pBl, n0, L, k0, st + PV_BL, tid);
    CP_ASYNC_COMMIT();
}

__global__ void __launch_bounds__(256, 2)
gemm_pv_kernel(const __nv_bfloat16* __restrict__ Ph, const __nv_bfloat16* __restrict__ Pl,
               const __nv_bfloat16* __restrict__ Bh, const __nv_bfloat16* __restrict__ Bl,
               float* __restrict__ O) {
    extern __shared__ char smem[];
    const uint32_t sb = smem_to_u32(smem);
    const int tid = threadIdx.x, wid = tid >> 5, lid = tid & 31;
    const int b  = blockIdx.z;
    const int m0 = blockIdx.y * 64;
    const int n0 = blockIdx.x * 128;

    const __nv_bfloat16* pAh = Ph + (size_t)b * L * L;
    const __nv_bfloat16* pAl = Pl + (size_t)b * L * L;
    const __nv_bfloat16* pBh = Bh + (size_t)b * D * L;
    const __nv_bfloat16* pBl = Bl + (size_t)b * D * L;

    const int rowbase = (wid & 1) * 32;
    const int colbase = (wid >> 1) * 32;
    const int lrow = lid & 15;
    const uint32_t lkoff = (uint32_t)((lid >> 4) * 16);

    float acc[2][4][4];
    #pragma unroll
    for (int mt = 0; mt < 2; mt++)
        #pragma unroll
        for (int nt = 0; nt < 4; nt++)
            #pragma unroll
            for (int r = 0; r < 4; r++) acc[mt][nt][r] = 0.0f;

    const int nch = L >> 6;

    pv_issue_stage(pAh, pAl, pBh, pBl, m0, n0, 0, sb, tid);

    for (int c = 0; c < nch; c++) {
        if (c + 1 < nch) {
            pv_issue_stage(pAh, pAl, pBh, pBl, m0, n0, (c + 1) << 6,
                           sb + (uint32_t)((c + 1) & 1) * PV_STAGE, tid);
            CP_ASYNC_WAIT(1);
        } else {
            CP_ASYNC_WAIT(0);
        }
        __syncthreads();

        const uint32_t st = sb + (uint32_t)(c & 1) * PV_STAGE;
        const uint32_t aH = st + PV_AH;
        const uint32_t aL = st + PV_AL;
        const uint32_t bH = st + PV_BH;
        const uint32_t bL = st + PV_BL;

        #pragma unroll
        for (int ks = 0; ks < 4; ks++) {
            const uint32_t kb = (uint32_t)(ks * 32) + lkoff;
            uint32_t ah[2][4], al[2][4];
            #pragma unroll
            for (int mt = 0; mt < 2; mt++) {
                const uint32_t boff = (uint32_t)((rowbase + mt * 16 + lrow) * 128) + kb;
                ldsm_x4(ah[mt][0], ah[mt][1], ah[mt][2], ah[mt][3], aH + SWZ(boff));
                ldsm_x4(al[mt][0], al[mt][1], al[mt][2], al[mt][3], aL + SWZ(boff));
            }
            #pragma unroll
            for (int np = 0; np < 2; np++) {
                const uint32_t boff = (uint32_t)((colbase + np * 16 + lrow) * 128) + kb;
                uint32_t bh[4], bl[4];
                ldsm_x4(bh[0], bh[1], bh[2], bh[3], bH + SWZ(boff));
                ldsm_x4(bl[0], bl[1], bl[2], bl[3], bL + SWZ(boff));
                #pragma unroll
                for (int mt = 0; mt < 2; mt++) {
                    float* c0 = acc[mt][np * 2 + 0];
                    float* c1 = acc[mt][np * 2 + 1];
                    mma_bf16(c0[0], c0[1], c0[2], c0[3],
                             ah[mt][0], ah[mt][1], ah[mt][2], ah[mt][3], bh[0], bh[2]);
                    mma_bf16(c1[0], c1[1], c1[2], c1[3],
                             ah[mt][0], ah[mt][1], ah[mt][2], ah[mt][3], bh[1], bh[3]);
                    mma_bf16(c0[0], c0[1], c0[2], c0[3],
                             ah[mt][0], ah[mt][1], ah[mt][2], ah[mt][3], bl[0], bl[2]);
                    mma_bf16(c1[0], c1[1], c1[2], c1[3],
                             ah[mt][0], ah[mt][1], ah[mt][2], ah[mt][3], bl[1], bl[3]);
                    mma_bf16(c0[0], c0[1], c0[2], c0[3],
                             al[mt][0], al[mt][1], al[mt][2], al[mt][3], bh[0], bh[2]);
                    mma_bf16(c1[0], c1[1], c1[2], c1[3],
                             al[mt][0], al[mt][1], al[mt][2], al[mt][3], bh[1], bh[3]);
                }
            }
        }
        __syncthreads();
    }

    float* pO = O + (size_t)b * L * D;
    const int trow = lid >> 2;
    const int tcol = (lid & 3) * 2;
    #pragma unroll
    for (int mt = 0; mt < 2; mt++) {
        #pragma unroll
        for (int nt = 0; nt < 4; nt++) {
            const int row = m0 + rowbase + mt * 16 + trow;
            const int col = n0 + colbase + nt * 8 + tcol;
            *(float2*)(pO + (size_t)row * D + col) =
                make_float2(acc[mt][nt][0], acc[mt][nt][1]);
            *(float2*)(pO + (size_t)(row + 8) * D + col) =
                make_float2(acc[mt][nt][2], acc[mt][nt][3]);
        }
    }
}

// ---------------------------------------------------------------------------
// softmax: one warp per row, barrier-free. 256 thr = 8 rows/block.
// Each lane owns 8 float4 (32 elements). Emits P fp32 + bf16 hi/lo.
// ---------------------------------------------------------------------------
__global__ void __launch_bounds__(256) softmax_kernel(float* __restrict__ attn) {
    const int wid = threadIdx.x >> 5, lid = threadIdx.x & 31;
    const size_t row = (size_t)blockIdx.x * 8 + wid;
    float* p = attn + row * L;
    __nv_bfloat16* ph = g_ph + row * L;
    __nv_bfloat16* pl = g_pl + row * L;

    float4 v[8];
    #pragma unroll
    for (int i = 0; i < 8; i++) v[i] = ((const float4*)p)[lid + 32 * i];

    float m = neg_inf();
    #pragma unroll
    for (int i = 0; i < 8; i++) {
        m = fmaxf(m, fmaxf(fmaxf(v[i].x, v[i].y), fmaxf(v[i].z, v[i].w)));
    }
    #pragma unroll
    for (int o = 16; o > 0; o >>= 1) m = fmaxf(m, __shfl_xor_sync(0xffffffffu, m, o));

    if (m == neg_inf()) {
        const float4 z4 = make_float4(0.f, 0.f, 0.f, 0.f);
        const uint2 z2 = make_uint2(0u, 0u);
        #pragma unroll
        for (int i = 0; i < 8; i++) {
            ((float4*)p)[lid + 32 * i] = z4;
            ((uint2*)ph)[lid + 32 * i] = z2;
            ((uint2*)pl)[lid + 32 * i] = z2;
        }
        return;
    }

    float s = 0.0f;
    #pragma unroll
    for (int i = 0; i < 8; i++) {
        v[i].x = __expf(v[i].x - m);
        v[i].y = __expf(v[i].y - m);
        v[i].z = __expf(v[i].z - m);
        v[i].w = __expf(v[i].w - m);
        s += (v[i].x + v[i].y) + (v[i].z + v[i].w);
    }
    #pragma unroll
    for (int o = 16; o > 0; o >>= 1) s += __shfl_xor_sync(0xffffffffu, s, o);
    const float inv = 1.0f / s;

    #pragma unroll
    for (int i = 0; i < 8; i++) {
        v[i].x *= inv; v[i].y *= inv; v[i].z *= inv; v[i].w *= inv;
        ((float4*)p)[lid + 32 * i] = v[i];

        __nv_bfloat16 h0 = __float2bfloat16(v[i].x), h1 = __float2bfloat16(v[i].y);
        __nv_bfloat16 h2 = __float2bfloat16(v[i].z), h3 = __float2bfloat16(v[i].w);
        __nv_bfloat16 l0 = __float2bfloat16(v[i].x - __bfloat162float(h0));
        __nv_bfloat16 l1 = __float2bfloat16(v[i].y - __bfloat162float(h1));
        __nv_bfloat16 l2 = __float2bfloat16(v[i].z - __bfloat162float(h2));
        __nv_bfloat16 l3 = __float2bfloat16(v[i].w - __bfloat162float(h3));
        __nv_bfloat162 hp0, hp1, lp0, lp1;
        hp0.x = h0; hp0.y = h1; hp1.x = h2; hp1.y = h3;
        lp0.x = l0; lp0.y = l1; lp1.x = l2; lp1.y = l3;
        uint2 hu, lu;
        hu.x = *(uint32_t*)&hp0; hu.y = *(uint32_t*)&hp1;
        lu.x = *(uint32_t*)&lp0; lu.y = *(uint32_t*)&lp1;
        ((uint2*)ph)[lid + 32 * i] = hu;
        ((uint2*)pl)[lid + 32 * i] = lu;
    }
}

// ---------------------------------------------------------------------------
// Launch
// ---------------------------------------------------------------------------
extern "C" void kernel_launch(void* const* d_in, const int* in_sizes, int n_in,
                              void* d_out, int out_size) {
    const float* q = (const float*)d_in[0];
    float* out  = (float*)d_out;
    float* attn = (float*)d_out + (size_t)B * L * D;

    void *qh, *ql, *qth, *qtl, *ph, *pl;
    cudaGetSymbolAddress(&qh,  g_qh);
    cudaGetSymbolAddress(&ql,  g_ql);
    cudaGetSymbolAddress(&qth, g_qth);
    cudaGetSymbolAddress(&qtl, g_qtl);
    cudaGetSymbolAddress(&ph,  g_ph);
    cudaGetSymbolAddress(&pl,  g_pl);

    cudaFuncSetAttribute(gemm_qqt_sym_kernel, cudaFuncAttributeMaxDynamicSharedMemorySize, G1_SMEM);
    cudaFuncSetAttribute(gemm_pv_kernel,      cudaFuncAttributeMaxDynamicSharedMemorySize, PV_SMEM);

    dim3 gs(D / 32, L / 32, B);
    split_q_kernel<<<gs, dim3(32, 8)>>>(q);

    dim3 g1(72, 1, B);
    gemm_qqt_sym_kernel<<<g1, 256, G1_SMEM>>>(
        (const __nv_bfloat16*)qh, (const __nv_bfloat16*)ql, attn);

    softmax_kernel<<<B * L / 8, 256>>>(attn);

    dim3 g2(D / 128, L / 64, B);
    gemm_pv_kernel<<<g2, 256, PV_SMEM>>>(
        (const __nv_bfloat16*)ph, (const __nv_bfloat16*)pl,
        (const __nv_bfloat16*)qth, (const __nv_bfloat16*)qtl, out);
}

// round 12
// speedup vs baseline: 1.3828x; 1.3171x over previous
#include <cuda_runtime.h>
#include <cuda_fp16.h>
#include <cstdint>

#define B   32
#define L   1024
#define D   256
#define INV_TEMP (1.0f/16.0f)

// ---------------------------------------------------------------------------
// Scratch (fp16 hi/lo)
// ---------------------------------------------------------------------------
__device__ __half g_qh [B * L * D];   // q hi   [B,L,D]
__device__ __half g_ql [B * L * D];   // q lo   [B,L,D]
__device__ __half g_qth[B * D * L];   // q^T hi [B,D,L]
__device__ __half g_qtl[B * D * L];   // q^T lo [B,D,L]
__device__ __half g_ph [B * L * L];   // softmax(P) hi only

// symmetric tile decode: 128-row block i, 64-col block j64, j64 >= 2i (72 tiles)
__constant__ uint8_t c_ti[72] = {
    0,0,0,0,0,0,0,0,0,0,0,0,0,0,0,0,
    1,1,1,1,1,1,1,1,1,1,1,1,1,1,
    2,2,2,2,2,2,2,2,2,2,2,2,
    3,3,3,3,3,3,3,3,3,3,
    4,4,4,4,4,4,4,4,
    5,5,5,5,5,5,
    6,6,6,6,
    7,7};
__constant__ uint8_t c_tj[72] = {
    0,1,2,3,4,5,6,7,8,9,10,11,12,13,14,15,
    2,3,4,5,6,7,8,9,10,11,12,13,14,15,
    4,5,6,7,8,9,10,11,12,13,14,15,
    6,7,8,9,10,11,12,13,14,15,
    8,9,10,11,12,13,14,15,
    10,11,12,13,14,15,
    12,13,14,15,
    14,15};

__device__ __forceinline__ float neg_inf() { return __int_as_float(0xff800000); }

__device__ __forceinline__ uint32_t smem_to_u32(const void* p) {
    uint32_t a;
    asm("{ .reg .u64 t; cvta.to.shared.u64 t, %1; cvt.u32.u64 %0, t; }" : "=r"(a) : "l"(p));
    return a;
}

#define SWZ(x) ((x) ^ (((x) >> 3) & 0x70))

__device__ __forceinline__ void ldsm_x4(uint32_t& r0, uint32_t& r1, uint32_t& r2, uint32_t& r3,
                                        uint32_t addr) {
    asm volatile("ldmatrix.sync.aligned.m8n8.x4.shared.b16 {%0,%1,%2,%3}, [%4];"
                 : "=r"(r0), "=r"(r1), "=r"(r2), "=r"(r3) : "r"(addr));
}

__device__ __forceinline__ void mma_f16(float& c0, float& c1, float& c2, float& c3,
                                        uint32_t a0, uint32_t a1, uint32_t a2, uint32_t a3,
                                        uint32_t b0, uint32_t b1) {
    asm volatile("mma.sync.aligned.m16n8k16.row.col.f32.f16.f16.f32 "
                 "{%0,%1,%2,%3}, {%4,%5,%6,%7}, {%8,%9}, {%0,%1,%2,%3};"
                 : "+f"(c0), "+f"(c1), "+f"(c2), "+f"(c3)
                 : "r"(a0), "r"(a1), "r"(a2), "r"(a3), "r"(b0), "r"(b1));
}

#define CP_ASYNC_16(dst, src) \
    asm volatile("cp.async.cg.shared.global [%0], [%1], 16;" :: "r"(dst), "l"(src))
#define CP_ASYNC_COMMIT() asm volatile("cp.async.commit_group;" ::: "memory")
#define CP_ASYNC_WAIT(n)  asm volatile("cp.async.wait_group %0;" :: "n"(n) : "memory")

// ---------------------------------------------------------------------------
// Kernel A: split q -> fp16 hi/lo + transposed hi/lo copies.
// ---------------------------------------------------------------------------
__global__ void __launch_bounds__(256) split_q_kernel(const float* __restrict__ q) {
    const int b  = blockIdx.z;
    const int d0 = blockIdx.x * 32;
    const int l0 = blockIdx.y * 32;
    const float* Q = q + (size_t)b * L * D;
    __shared__ float t[32][33];
    const int tx = threadIdx.x, ty = threadIdx.y;

    #pragma unroll
    for (int i = 0; i < 4; i++) {
        const int r = ty + i * 8;
        const float v = Q[(size_t)(l0 + r) * D + d0 + tx];
        t[r][tx] = v;
        __half h  = __float2half_rn(v);
        __half lo = __float2half_rn(v - __half2float(h));
        const size_t idx = (size_t)b * L * D + (size_t)(l0 + r) * D + d0 + tx;
        g_qh[idx] = h;
        g_ql[idx] = lo;
    }
    __syncthreads();
    #pragma unroll
    for (int i = 0; i < 4; i++) {
        const int r = ty + i * 8;
        const float v = t[tx][r];
        __half h  = __float2half_rn(v);
        __half lo = __float2half_rn(v - __half2float(h));
        const size_t idx = (size_t)b * D * L + (size_t)(d0 + r) * L + l0 + tx;
        g_qth[idx] = h;
        g_qtl[idx] = lo;
    }
}

// ---------------------------------------------------------------------------
// Generic tile loader: ROWS x 64 fp16, 128B swizzled rows, NT threads.
// ---------------------------------------------------------------------------
template <int ROWS, int NT>
__device__ __forceinline__ void issue_tile(const __half* __restrict__ src,
                                           int row0, int ld, int k0,
                                           uint32_t smem_tile, int tid) {
    #pragma unroll
    for (int i = 0; i < (ROWS * 8) / NT; i++) {
        const int chunk = tid + i * NT;
        const int row = chunk >> 3;
        const int c16 = chunk & 7;
        const __half* g = src + (size_t)(row0 + row) * ld + k0 + c16 * 8;
        CP_ASYNC_16(smem_tile + SWZ((uint32_t)(row * 128 + c16 * 16)), g);
    }
}

// ===========================================================================
// GEMM1 (symmetric): S = Q@Q^T, 2-term fp16: (A=qh) @ (Bh=qh) + (A=qh) @ (Bl=ql)
// i.e. Ah@Bh + Ah@Bl  ==  qh @ q  (error = ql@q ~ 2^-13 rel).
// CTA tile 128x64, 8 warps (4x2), warp tile 32x32, 2-stage.
// stage = A 16KB + Bh 8KB + Bl 8KB = 32KB; 64KB total -> 2 CTAs/SM.
// ===========================================================================
#define G1_TA 16384
#define G1_TB 8192
#define G1_STAGE (G1_TA + 2 * G1_TB)     // 32KB
#define G1_SMEM (2 * G1_STAGE)           // 64KB
#define G1_A  0
#define G1_BH G1_TA
#define G1_BL (G1_TA + G1_TB)

__device__ __forceinline__ void g1_issue_stage(
        const __half* pQh, const __half* pQl,
        int m0, int n0, int k0, uint32_t st, int tid) {
    issue_tile<128, 256>(pQh, m0, D, k0, st + G1_A, tid);
    issue_tile<64, 256>(pQh, n0, D, k0, st + G1_BH, tid);
    issue_tile<64, 256>(pQl, n0, D, k0, st + G1_BL, tid);
    CP_ASYNC_COMMIT();
}

__global__ void __launch_bounds__(256, 2)
gemm_qqt_sym_kernel(const __half* __restrict__ Qh, const __half* __restrict__ Ql,
                    float* __restrict__ S) {
    extern __shared__ char smem[];
    const uint32_t sb = smem_to_u32(smem);
    const int tid = threadIdx.x, wid = tid >> 5, lid = tid & 31;
    const int b   = blockIdx.z;
    const int bi  = c_ti[blockIdx.x];
    const int bj64 = c_tj[blockIdx.x];
    const int m0 = bi * 128;
    const int n0 = bj64 * 64;

    const __half* pQh = Qh + (size_t)b * L * D;
    const __half* pQl = Ql + (size_t)b * L * D;

    const int rowbase = (wid & 3) * 32;
    const int colbase = (wid >> 2) * 32;
    const int lrow = lid & 15;
    const uint32_t lkoff = (uint32_t)((lid >> 4) * 16);

    float acc[2][4][4];
    #pragma unroll
    for (int mt = 0; mt < 2; mt++)
        #pragma unroll
        for (int nt = 0; nt < 4; nt++)
            #pragma unroll
            for (int r = 0; r < 4; r++) acc[mt][nt][r] = 0.0f;

    const int nch = D >> 6;
    g1_issue_stage(pQh, pQl, m0, n0, 0, sb, tid);

    for (int c = 0; c < nch; c++) {
        if (c + 1 < nch) {
            g1_issue_stage(pQh, pQl, m0, n0, (c + 1) << 6,
                           sb + (uint32_t)((c + 1) & 1) * G1_STAGE, tid);
            CP_ASYNC_WAIT(1);
        } else {
            CP_ASYNC_WAIT(0);
        }
        __syncthreads();

        const uint32_t st = sb + (uint32_t)(c & 1) * G1_STAGE;
        const uint32_t aA = st + G1_A;
        const uint32_t bH = st + G1_BH;
        const uint32_t bL = st + G1_BL;

        #pragma unroll
        for (int ks = 0; ks < 4; ks++) {
            const uint32_t kb = (uint32_t)(ks * 32) + lkoff;
            uint32_t ah[2][4];
            #pragma unroll
            for (int mt = 0; mt < 2; mt++) {
                const uint32_t boff = (uint32_t)((rowbase + mt * 16 + lrow) * 128) + kb;
                ldsm_x4(ah[mt][0], ah[mt][1], ah[mt][2], ah[mt][3], aA + SWZ(boff));
            }
            #pragma unroll
            for (int np = 0; np < 2; np++) {
                const uint32_t boff = (uint32_t)((colbase + np * 16 + lrow) * 128) + kb;
                uint32_t bh[4], bl[4];
                ldsm_x4(bh[0], bh[1], bh[2], bh[3], bH + SWZ(boff));
                ldsm_x4(bl[0], bl[1], bl[2], bl[3], bL + SWZ(boff));
                #pragma unroll
                for (int mt = 0; mt < 2; mt++) {
                    float* c0 = acc[mt][np * 2 + 0];
                    float* c1 = acc[mt][np * 2 + 1];
                    mma_f16(c0[0], c0[1], c0[2], c0[3],
                            ah[mt][0], ah[mt][1], ah[mt][2], ah[mt][3], bh[0], bh[2]);
                    mma_f16(c1[0], c1[1], c1[2], c1[3],
                            ah[mt][0], ah[mt][1], ah[mt][2], ah[mt][3], bh[1], bh[3]);
                    mma_f16(c0[0], c0[1], c0[2], c0[3],
                            ah[mt][0], ah[mt][1], ah[mt][2], ah[mt][3], bl[0], bl[2]);
                    mma_f16(c1[0], c1[1], c1[2], c1[3],
                            ah[mt][0], ah[mt][1], ah[mt][2], ah[mt][3], bl[1], bl[3]);
                }
            }
        }
        __syncthreads();
    }

    #pragma unroll
    for (int mt = 0; mt < 2; mt++)
        #pragma unroll
        for (int nt = 0; nt < 4; nt++)
            #pragma unroll
            for (int r = 0; r < 4; r++) {
                float v = acc[mt][nt][r];
                acc[mt][nt][r] = (v == 0.0f) ? neg_inf() : v * INV_TEMP;
            }

    float* pS = S + (size_t)b * L * L;
    const int trow = lid >> 2;
    const int tcol = (lid & 3) * 2;

    #pragma unroll
    for (int mt = 0; mt < 2; mt++) {
        #pragma unroll
        for (int nt = 0; nt < 4; nt++) {
            const int row = m0 + rowbase + mt * 16 + trow;
            const int col = n0 + colbase + nt * 8 + tcol;
            *(float2*)(pS + (size_t)row * L + col) =
                make_float2(acc[mt][nt][0], acc[mt][nt][1]);
            *(float2*)(pS + (size_t)(row + 8) * L + col) =
                make_float2(acc[mt][nt][2], acc[mt][nt][3]);
        }
    }

    if ((bj64 >> 1) > bi) {
        float* smemT = (float*)smem;
        #pragma unroll
        for (int mt = 0; mt < 2; mt++) {
            #pragma unroll
            for (int nt = 0; nt < 4; nt++) {
                const int i0 = rowbase + mt * 16 + trow;
                const int j0 = colbase + nt * 8 + tcol;
                smemT[(j0 + 0) * 132 + i0]     = acc[mt][nt][0];
                smemT[(j0 + 1) * 132 + i0]     = acc[mt][nt][1];
                smemT[(j0 + 0) * 132 + i0 + 8] = acc[mt][nt][2];
                smemT[(j0 + 1) * 132 + i0 + 8] = acc[mt][nt][3];
            }
        }
        __syncthreads();
        const int j       = tid >> 2;
        const int quarter = (tid & 3) * 32;
        float* dst = pS + (size_t)(n0 + j) * L + m0 + quarter;
        const float* srcrow = smemT + j * 132 + quarter;
        #pragma unroll
        for (int u = 0; u < 8; u++) {
            *(float4*)(dst + u * 4) = *(const float4*)(srcrow + u * 4);
        }
    }
}

// ===========================================================================
// GEMM2: O = P @ Q, 2-term fp16: Ph @ (qt_h + qt_l) == Ph @ q.
// CTA 64x128, 8 warps (2x4), warp tile 32x32, 2-stage.
// stage = A 8KB + Bh 16KB + Bl 16KB = 40KB; 80KB total -> 2 CTAs/SM.
// ===========================================================================
#define PV_TA 8192
#define PV_TB 16384
#define PV_STAGE (PV_TA + 2 * PV_TB)     // 40KB
#define PV_SMEM (2 * PV_STAGE)           // 80KB
#define PV_A  0
#define PV_BH PV_TA
#define PV_BL (PV_TA + PV_TB)

__device__ __forceinline__ void pv_issue_stage(
        const __half* pPh,
        const __half* pBh, const __half* pBl,
        int m0, int n0, int k0, uint32_t st, int tid) {
    issue_tile<64, 256>(pPh, m0, L, k0, st + PV_A, tid);
    issue_tile<128, 256>(pBh, n0, L, k0, st + PV_BH, tid);
    issue_tile<128, 256>(pBl, n0, L, k0, st + PV_BL, tid);
    CP_ASYNC_COMMIT();
}

__global__ void __launch_bounds__(256, 2)
gemm_pv_kernel(const __half* __restrict__ Ph,
               const __half* __restrict__ Bh, const __half* __restrict__ Bl,
               float* __restrict__ O) {
    extern __shared__ char smem[];
    const uint32_t sb = smem_to_u32(smem);
    const int tid = threadIdx.x, wid = tid >> 5, lid = tid & 31;
    const int b  = blockIdx.z;
    const int m0 = blockIdx.y * 64;
    const int n0 = blockIdx.x * 128;

    const __half* pPh = Ph + (size_t)b * L * L;
    const __half* pBh = Bh + (size_t)b * D * L;
    const __half* pBl = Bl + (size_t)b * D * L;

    const int rowbase = (wid & 1) * 32;
    const int colbase = (wid >> 1) * 32;
    const int lrow = lid & 15;
    const uint32_t lkoff = (uint32_t)((lid >> 4) * 16);

    float acc[2][4][4];
    #pragma unroll
    for (int mt = 0; mt < 2; mt++)
        #pragma unroll
        for (int nt = 0; nt < 4; nt++)
            #pragma unroll
            for (int r = 0; r < 4; r++) acc[mt][nt][r] = 0.0f;

    const int nch = L >> 6;

    pv_issue_stage(pPh, pBh, pBl, m0, n0, 0, sb, tid);

    for (int c = 0; c < nch; c++) {
        if (c + 1 < nch) {
            pv_issue_stage(pPh, pBh, pBl, m0, n0, (c + 1) << 6,
                           sb + (uint32_t)((c + 1) & 1) * PV_STAGE, tid);
            CP_ASYNC_WAIT(1);
        } else {
            CP_ASYNC_WAIT(0);
        }
        __syncthreads();

        const uint32_t st = sb + (uint32_t)(c & 1) * PV_STAGE;
        const uint32_t aA = st + PV_A;
        const uint32_t bH = st + PV_BH;
        const uint32_t bL = st + PV_BL;

        #pragma unroll
        for (int ks = 0; ks < 4; ks++) {
            const uint32_t kb = (uint32_t)(ks * 32) + lkoff;
            uint32_t ah[2][4];
            #pragma unroll
            for (int mt = 0; mt < 2; mt++) {
                const uint32_t boff = (uint32_t)((rowbase + mt * 16 + lrow) * 128) + kb;
                ldsm_x4(ah[mt][0], ah[mt][1], ah[mt][2], ah[mt][3], aA + SWZ(boff));
            }
            #pragma unroll
            for (int np = 0; np < 2; np++) {
                const uint32_t boff = (uint32_t)((colbase + np * 16 + lrow) * 128) + kb;
                uint32_t bh[4], bl[4];
                ldsm_x4(bh[0], bh[1], bh[2], bh[3], bH + SWZ(boff));
                ldsm_x4(bl[0], bl[1], bl[2], bl[3], bL + SWZ(boff));
                #pragma unroll
                for (int mt = 0; mt < 2; mt++) {
                    float* c0 = acc[mt][np * 2 + 0];
                    float* c1 = acc[mt][np * 2 + 1];
                    mma_f16(c0[0], c0[1], c0[2], c0[3],
                            ah[mt][0], ah[mt][1], ah[mt][2], ah[mt][3], bh[0], bh[2]);
                    mma_f16(c1[0], c1[1], c1[2], c1[3],
                            ah[mt][0], ah[mt][1], ah[mt][2], ah[mt][3], bh[1], bh[3]);
                    mma_f16(c0[0], c0[1], c0[2], c0[3],
                            ah[mt][0], ah[mt][1], ah[mt][2], ah[mt][3], bl[0], bl[2]);
                    mma_f16(c1[0], c1[1], c1[2], c1[3],
                            ah[mt][0], ah[mt][1], ah[mt][2], ah[mt][3], bl[1], bl[3]);
                }
            }
        }
        __syncthreads();
    }

    float* pO = O + (size_t)b * L * D;
    const int trow = lid >> 2;
    const int tcol = (lid & 3) * 2;
    #pragma unroll
    for (int mt = 0; mt < 2; mt++) {
        #pragma unroll
        for (int nt = 0; nt < 4; nt++) {
            const int row = m0 + rowbase + mt * 16 + trow;
            const int col = n0 + colbase + nt * 8 + tcol;
            *(float2*)(pO + (size_t)row * D + col) =
                make_float2(acc[mt][nt][0], acc[mt][nt][1]);
            *(float2*)(pO + (size_t)(row + 8) * D + col) =
                make_float2(acc[mt][nt][2], acc[mt][nt][3]);
        }
    }
}

// ---------------------------------------------------------------------------
// softmax: one warp per row, barrier-free. Emits P fp32 + fp16 hi ONLY.
// ---------------------------------------------------------------------------
__global__ void __launch_bounds__(256) softmax_kernel(float* __restrict__ attn) {
    const int wid = threadIdx.x >> 5, lid = threadIdx.x & 31;
    const size_t row = (size_t)blockIdx.x * 8 + wid;
    float* p = attn + row * L;
    __half* ph = g_ph + row * L;

    float4 v[8];
    #pragma unroll
    for (int i = 0; i < 8; i++) v[i] = ((const float4*)p)[lid + 32 * i];

    float m = neg_inf();
    #pragma unroll
    for (int i = 0; i < 8; i++) {
        m = fmaxf(m, fmaxf(fmaxf(v[i].x, v[i].y), fmaxf(v[i].z, v[i].w)));
    }
    #pragma unroll
    for (int o = 16; o > 0; o >>= 1) m = fmaxf(m, __shfl_xor_sync(0xffffffffu, m, o));

    if (m == neg_inf()) {
        const float4 z4 = make_float4(0.f, 0.f, 0.f, 0.f);
        const uint2 z2 = make_uint2(0u, 0u);
        #pragma unroll
        for (int i = 0; i < 8; i++) {
            ((float4*)p)[lid + 32 * i] = z4;
            ((uint2*)ph)[lid + 32 * i] = z2;
        }
        return;
    }

    float s = 0.0f;
    #pragma unroll
    for (int i = 0; i < 8; i++) {
        v[i].x = __expf(v[i].x - m);
        v[i].y = __expf(v[i].y - m);
        v[i].z = __expf(v[i].z - m);
        v[i].w = __expf(v[i].w - m);
        s += (v[i].x + v[i].y) + (v[i].z + v[i].w);
    }
    #pragma unroll
    for (int o = 16; o > 0; o >>= 1) s += __shfl_xor_sync(0xffffffffu, s, o);
    const float inv = 1.0f / s;

    #pragma unroll
    for (int i = 0; i < 8; i++) {
        v[i].x *= inv; v[i].y *= inv; v[i].z *= inv; v[i].w *= inv;
        ((float4*)p)[lid + 32 * i] = v[i];

        __half2 hp0 = __floats2half2_rn(v[i].x, v[i].y);
        __half2 hp1 = __floats2half2_rn(v[i].z, v[i].w);
        uint2 hu;
        hu.x = *(uint32_t*)&hp0;
        hu.y = *(uint32_t*)&hp1;
        ((uint2*)ph)[lid + 32 * i] = hu;
    }
}

// ---------------------------------------------------------------------------
// Launch
// ---------------------------------------------------------------------------
extern "C" void kernel_launch(void* const* d_in, const int* in_sizes, int n_in,
                              void* d_out, int out_size) {
    const float* q = (const float*)d_in[0];
    float* out  = (float*)d_out;
    float* attn = (float*)d_out + (size_t)B * L * D;

    void *qh, *ql, *qth, *qtl, *ph;
    cudaGetSymbolAddress(&qh,  g_qh);
    cudaGetSymbolAddress(&ql,  g_ql);
    cudaGetSymbolAddress(&qth, g_qth);
    cudaGetSymbolAddress(&qtl, g_qtl);
    cudaGetSymbolAddress(&ph,  g_ph);

    cudaFuncSetAttribute(gemm_qqt_sym_kernel, cudaFuncAttributeMaxDynamicSharedMemorySize, G1_SMEM);
    cudaFuncSetAttribute(gemm_pv_kernel,      cudaFuncAttributeMaxDynamicSharedMemorySize, PV_SMEM);

    dim3 gs(D / 32, L / 32, B);
    split_q_kernel<<<gs, dim3(32, 8)>>>(q);

    dim3 g1(72, 1, B);
    gemm_qqt_sym_kernel<<<g1, 256, G1_SMEM>>>(
        (const __half*)qh, (const __half*)ql, attn);

    softmax_kernel<<<B * L / 8, 256>>>(attn);

    dim3 g2(D / 128, L / 64, B);
    gemm_pv_kernel<<<g2, 256, PV_SMEM>>>(
        (const __half*)ph,
        (const __half*)qth, (const __half*)qtl, out);
}

// round 13
// speedup vs baseline: 1.6238x; 1.1743x over previous
#include <cuda_runtime.h>
#include <cuda_fp16.h>
#include <cstdint>

#define B   32
#define L   1024
#define D   256
#define INV_TEMP (1.0f/16.0f)

// ---------------------------------------------------------------------------
// Scratch (fp16)
// ---------------------------------------------------------------------------
__device__ __half g_qh [B * L * D];   // q hi   [B,L,D]
__device__ __half g_ql [B * L * D];   // q lo   [B,L,D]  (GEMM1 B-side only)
__device__ __half g_qth[B * D * L];   // q^T hi [B,D,L]  (pv B-side)
__device__ __half g_ph [B * L * L];   // softmax(P) fp16

// symmetric tile decode: 128-row block i, 64-col block j64, j64 >= 2i (72 tiles)
__constant__ uint8_t c_ti[72] = {
    0,0,0,0,0,0,0,0,0,0,0,0,0,0,0,0,
    1,1,1,1,1,1,1,1,1,1,1,1,1,1,
    2,2,2,2,2,2,2,2,2,2,2,2,
    3,3,3,3,3,3,3,3,3,3,
    4,4,4,4,4,4,4,4,
    5,5,5,5,5,5,
    6,6,6,6,
    7,7};
__constant__ uint8_t c_tj[72] = {
    0,1,2,3,4,5,6,7,8,9,10,11,12,13,14,15,
    2,3,4,5,6,7,8,9,10,11,12,13,14,15,
    4,5,6,7,8,9,10,11,12,13,14,15,
    6,7,8,9,10,11,12,13,14,15,
    8,9,10,11,12,13,14,15,
    10,11,12,13,14,15,
    12,13,14,15,
    14,15};

__device__ __forceinline__ float neg_inf() { return __int_as_float(0xff800000); }

__device__ __forceinline__ uint32_t smem_to_u32(const void* p) {
    uint32_t a;
    asm("{ .reg .u64 t; cvta.to.shared.u64 t, %1; cvt.u32.u64 %0, t; }" : "=r"(a) : "l"(p));
    return a;
}

#define SWZ(x) ((x) ^ (((x) >> 3) & 0x70))

__device__ __forceinline__ void ldsm_x4(uint32_t& r0, uint32_t& r1, uint32_t& r2, uint32_t& r3,
                                        uint32_t addr) {
    asm volatile("ldmatrix.sync.aligned.m8n8.x4.shared.b16 {%0,%1,%2,%3}, [%4];"
                 : "=r"(r0), "=r"(r1), "=r"(r2), "=r"(r3) : "r"(addr));
}

__device__ __forceinline__ void mma_f16(float& c0, float& c1, float& c2, float& c3,
                                        uint32_t a0, uint32_t a1, uint32_t a2, uint32_t a3,
                                        uint32_t b0, uint32_t b1) {
    asm volatile("mma.sync.aligned.m16n8k16.row.col.f32.f16.f16.f32 "
                 "{%0,%1,%2,%3}, {%4,%5,%6,%7}, {%8,%9}, {%0,%1,%2,%3};"
                 : "+f"(c0), "+f"(c1), "+f"(c2), "+f"(c3)
                 : "r"(a0), "r"(a1), "r"(a2), "r"(a3), "r"(b0), "r"(b1));
}

#define CP_ASYNC_16(dst, src) \
    asm volatile("cp.async.cg.shared.global [%0], [%1], 16;" :: "r"(dst), "l"(src))
#define CP_ASYNC_COMMIT() asm volatile("cp.async.commit_group;" ::: "memory")
#define CP_ASYNC_WAIT(n)  asm volatile("cp.async.wait_group %0;" :: "n"(n) : "memory")

// ---------------------------------------------------------------------------
// Kernel A: split q -> fp16 hi/lo + transposed hi copy.
// ---------------------------------------------------------------------------
__global__ void __launch_bounds__(256) split_q_kernel(const float* __restrict__ q) {
    const int b  = blockIdx.z;
    const int d0 = blockIdx.x * 32;
    const int l0 = blockIdx.y * 32;
    const float* Q = q + (size_t)b * L * D;
    __shared__ float t[32][33];
    const int tx = threadIdx.x, ty = threadIdx.y;

    #pragma unroll
    for (int i = 0; i < 4; i++) {
        const int r = ty + i * 8;
        const float v = Q[(size_t)(l0 + r) * D + d0 + tx];
        t[r][tx] = v;
        __half h  = __float2half_rn(v);
        __half lo = __float2half_rn(v - __half2float(h));
        const size_t idx = (size_t)b * L * D + (size_t)(l0 + r) * D + d0 + tx;
        g_qh[idx] = h;
        g_ql[idx] = lo;
    }
    __syncthreads();
    #pragma unroll
    for (int i = 0; i < 4; i++) {
        const int r = ty + i * 8;
        const float v = t[tx][r];
        const size_t idx = (size_t)b * D * L + (size_t)(d0 + r) * L + l0 + tx;
        g_qth[idx] = __float2half_rn(v);
    }
}

// ---------------------------------------------------------------------------
// Generic tile loader: ROWS x 64 fp16, 128B swizzled rows, NT threads.
// ---------------------------------------------------------------------------
template <int ROWS, int NT>
__device__ __forceinline__ void issue_tile(const __half* __restrict__ src,
                                           int row0, int ld, int k0,
                                           uint32_t smem_tile, int tid) {
    #pragma unroll
    for (int i = 0; i < (ROWS * 8) / NT; i++) {
        const int chunk = tid + i * NT;
        const int row = chunk >> 3;
        const int c16 = chunk & 7;
        const __half* g = src + (size_t)(row0 + row) * ld + k0 + c16 * 8;
        CP_ASYNC_16(smem_tile + SWZ((uint32_t)(row * 128 + c16 * 16)), g);
    }
}

// ===========================================================================
// GEMM1 (symmetric): S = Q@Q^T, 2-term fp16 (qh @ qh + qh @ ql == qh @ q).
// CTA tile 128x64, 8 warps (4x2), warp tile 32x32, 2-stage, 64KB -> 2 CTAs/SM.
// ===========================================================================
#define G1_TA 16384
#define G1_TB 8192
#define G1_STAGE (G1_TA + 2 * G1_TB)     // 32KB
#define G1_SMEM (2 * G1_STAGE)           // 64KB
#define G1_A  0
#define G1_BH G1_TA
#define G1_BL (G1_TA + G1_TB)

__device__ __forceinline__ void g1_issue_stage(
        const __half* pQh, const __half* pQl,
        int m0, int n0, int k0, uint32_t st, int tid) {
    issue_tile<128, 256>(pQh, m0, D, k0, st + G1_A, tid);
    issue_tile<64, 256>(pQh, n0, D, k0, st + G1_BH, tid);
    issue_tile<64, 256>(pQl, n0, D, k0, st + G1_BL, tid);
    CP_ASYNC_COMMIT();
}

__global__ void __launch_bounds__(256, 2)
gemm_qqt_sym_kernel(const __half* __restrict__ Qh, const __half* __restrict__ Ql,
                    float* __restrict__ S) {
    extern __shared__ char smem[];
    const uint32_t sb = smem_to_u32(smem);
    const int tid = threadIdx.x, wid = tid >> 5, lid = tid & 31;
    const int b   = blockIdx.z;
    const int bi  = c_ti[blockIdx.x];
    const int bj64 = c_tj[blockIdx.x];
    const int m0 = bi * 128;
    const int n0 = bj64 * 64;

    const __half* pQh = Qh + (size_t)b * L * D;
    const __half* pQl = Ql + (size_t)b * L * D;

    const int rowbase = (wid & 3) * 32;
    const int colbase = (wid >> 2) * 32;
    const int lrow = lid & 15;
    const uint32_t lkoff = (uint32_t)((lid >> 4) * 16);

    float acc[2][4][4];
    #pragma unroll
    for (int mt = 0; mt < 2; mt++)
        #pragma unroll
        for (int nt = 0; nt < 4; nt++)
            #pragma unroll
            for (int r = 0; r < 4; r++) acc[mt][nt][r] = 0.0f;

    const int nch = D >> 6;
    g1_issue_stage(pQh, pQl, m0, n0, 0, sb, tid);

    for (int c = 0; c < nch; c++) {
        if (c + 1 < nch) {
            g1_issue_stage(pQh, pQl, m0, n0, (c + 1) << 6,
                           sb + (uint32_t)((c + 1) & 1) * G1_STAGE, tid);
            CP_ASYNC_WAIT(1);
        } else {
            CP_ASYNC_WAIT(0);
        }
        __syncthreads();

        const uint32_t st = sb + (uint32_t)(c & 1) * G1_STAGE;
        const uint32_t aA = st + G1_A;
        const uint32_t bH = st + G1_BH;
        const uint32_t bL = st + G1_BL;

        #pragma unroll
        for (int ks = 0; ks < 4; ks++) {
            const uint32_t kb = (uint32_t)(ks * 32) + lkoff;
            uint32_t ah[2][4];
            #pragma unroll
            for (int mt = 0; mt < 2; mt++) {
                const uint32_t boff = (uint32_t)((rowbase + mt * 16 + lrow) * 128) + kb;
                ldsm_x4(ah[mt][0], ah[mt][1], ah[mt][2], ah[mt][3], aA + SWZ(boff));
            }
            #pragma unroll
            for (int np = 0; np < 2; np++) {
                const uint32_t boff = (uint32_t)((colbase + np * 16 + lrow) * 128) + kb;
                uint32_t bh[4], bl[4];
                ldsm_x4(bh[0], bh[1], bh[2], bh[3], bH + SWZ(boff));
                ldsm_x4(bl[0], bl[1], bl[2], bl[3], bL + SWZ(boff));
                #pragma unroll
                for (int mt = 0; mt < 2; mt++) {
                    float* c0 = acc[mt][np * 2 + 0];
                    float* c1 = acc[mt][np * 2 + 1];
                    mma_f16(c0[0], c0[1], c0[2], c0[3],
                            ah[mt][0], ah[mt][1], ah[mt][2], ah[mt][3], bh[0], bh[2]);
                    mma_f16(c1[0], c1[1], c1[2], c1[3],
                            ah[mt][0], ah[mt][1], ah[mt][2], ah[mt][3], bh[1], bh[3]);
                    mma_f16(c0[0], c0[1], c0[2], c0[3],
                            ah[mt][0], ah[mt][1], ah[mt][2], ah[mt][3], bl[0], bl[2]);
                    mma_f16(c1[0], c1[1], c1[2], c1[3],
                            ah[mt][0], ah[mt][1], ah[mt][2], ah[mt][3], bl[1], bl[3]);
                }
            }
        }
        __syncthreads();
    }

    #pragma unroll
    for (int mt = 0; mt < 2; mt++)
        #pragma unroll
        for (int nt = 0; nt < 4; nt++)
            #pragma unroll
            for (int r = 0; r < 4; r++) {
                float v = acc[mt][nt][r];
                acc[mt][nt][r] = (v == 0.0f) ? neg_inf() : v * INV_TEMP;
            }

    float* pS = S + (size_t)b * L * L;
    const int trow = lid >> 2;
    const int tcol = (lid & 3) * 2;

    #pragma unroll
    for (int mt = 0; mt < 2; mt++) {
        #pragma unroll
        for (int nt = 0; nt < 4; nt++) {
            const int row = m0 + rowbase + mt * 16 + trow;
            const int col = n0 + colbase + nt * 8 + tcol;
            *(float2*)(pS + (size_t)row * L + col) =
                make_float2(acc[mt][nt][0], acc[mt][nt][1]);
            *(float2*)(pS + (size_t)(row + 8) * L + col) =
                make_float2(acc[mt][nt][2], acc[mt][nt][3]);
        }
    }

    if ((bj64 >> 1) > bi) {
        float* smemT = (float*)smem;
        #pragma unroll
        for (int mt = 0; mt < 2; mt++) {
            #pragma unroll
            for (int nt = 0; nt < 4; nt++) {
                const int i0 = rowbase + mt * 16 + trow;
                const int j0 = colbase + nt * 8 + tcol;
                smemT[(j0 + 0) * 132 + i0]     = acc[mt][nt][0];
                smemT[(j0 + 1) * 132 + i0]     = acc[mt][nt][1];
                smemT[(j0 + 0) * 132 + i0 + 8] = acc[mt][nt][2];
                smemT[(j0 + 1) * 132 + i0 + 8] = acc[mt][nt][3];
            }
        }
        __syncthreads();
        const int j       = tid >> 2;
        const int quarter = (tid & 3) * 32;
        float* dst = pS + (size_t)(n0 + j) * L + m0 + quarter;
        const float* srcrow = smemT + j * 132 + quarter;
        #pragma unroll
        for (int u = 0; u < 8; u++) {
            *(float4*)(dst + u * 4) = *(const float4*)(srcrow + u * 4);
        }
    }
}

// ===========================================================================
// GEMM2: O = Ph @ qt_h (single term; P's own fp16 rounding dominates error).
// CTA 64x128, 8 warps (2x4), warp tile 32x32, 2-stage.
// stage = A 8KB + B 16KB = 24KB; 48KB total -> 2 CTAs/SM.
// ===========================================================================
#define PV_TA 8192
#define PV_TB 16384
#define PV_STAGE (PV_TA + PV_TB)         // 24KB
#define PV_SMEM (2 * PV_STAGE)           // 48KB
#define PV_A  0
#define PV_B  PV_TA

__device__ __forceinline__ void pv_issue_stage(
        const __half* pPh, const __half* pBh,
        int m0, int n0, int k0, uint32_t st, int tid) {
    issue_tile<64, 256>(pPh, m0, L, k0, st + PV_A, tid);
    issue_tile<128, 256>(pBh, n0, L, k0, st + PV_B, tid);
    CP_ASYNC_COMMIT();
}

__global__ void __launch_bounds__(256, 2)
gemm_pv_kernel(const __half* __restrict__ Ph,
               const __half* __restrict__ Bh,
               float* __restrict__ O) {
    extern __shared__ char smem[];
    const uint32_t sb = smem_to_u32(smem);
    const int tid = threadIdx.x, wid = tid >> 5, lid = tid & 31;
    const int b  = blockIdx.z;
    const int m0 = blockIdx.y * 64;
    const int n0 = blockIdx.x * 128;

    const __half* pPh = Ph + (size_t)b * L * L;
    const __half* pBh = Bh + (size_t)b * D * L;

    const int rowbase = (wid & 1) * 32;
    const int colbase = (wid >> 1) * 32;
    const int lrow = lid & 15;
    const uint32_t lkoff = (uint32_t)((lid >> 4) * 16);

    float acc[2][4][4];
    #pragma unroll
    for (int mt = 0; mt < 2; mt++)
        #pragma unroll
        for (int nt = 0; nt < 4; nt++)
            #pragma unroll
            for (int r = 0; r < 4; r++) acc[mt][nt][r] = 0.0f;

    const int nch = L >> 6;

    pv_issue_stage(pPh, pBh, m0, n0, 0, sb, tid);

    for (int c = 0; c < nch; c++) {
        if (c + 1 < nch) {
            pv_issue_stage(pPh, pBh, m0, n0, (c + 1) << 6,
                           sb + (uint32_t)((c + 1) & 1) * PV_STAGE, tid);
            CP_ASYNC_WAIT(1);
        } else {
            CP_ASYNC_WAIT(0);
        }
        __syncthreads();

        const uint32_t st = sb + (uint32_t)(c & 1) * PV_STAGE;
        const uint32_t aA = st + PV_A;
        const uint32_t bB = st + PV_B;

        #pragma unroll
        for (int ks = 0; ks < 4; ks++) {
            const uint32_t kb = (uint32_t)(ks * 32) + lkoff;
            uint32_t ah[2][4];
            #pragma unroll
            for (int mt = 0; mt < 2; mt++) {
                const uint32_t boff = (uint32_t)((rowbase + mt * 16 + lrow) * 128) + kb;
                ldsm_x4(ah[mt][0], ah[mt][1], ah[mt][2], ah[mt][3], aA + SWZ(boff));
            }
            #pragma unroll
            for (int np = 0; np < 2; np++) {
                const uint32_t boff = (uint32_t)((colbase + np * 16 + lrow) * 128) + kb;
                uint32_t bh[4];
                ldsm_x4(bh[0], bh[1], bh[2], bh[3], bB + SWZ(boff));
                #pragma unroll
                for (int mt = 0; mt < 2; mt++) {
                    float* c0 = acc[mt][np * 2 + 0];
                    float* c1 = acc[mt][np * 2 + 1];
                    mma_f16(c0[0], c0[1], c0[2], c0[3],
                            ah[mt][0], ah[mt][1], ah[mt][2], ah[mt][3], bh[0], bh[2]);
                    mma_f16(c1[0], c1[1], c1[2], c1[3],
                            ah[mt][0], ah[mt][1], ah[mt][2], ah[mt][3], bh[1], bh[3]);
                }
            }
        }
        __syncthreads();
    }

    float* pO = O + (size_t)b * L * D;
    const int trow = lid >> 2;
    const int tcol = (lid & 3) * 2;
    #pragma unroll
    for (int mt = 0; mt < 2; mt++) {
        #pragma unroll
        for (int nt = 0; nt < 4; nt++) {
            const int row = m0 + rowbase + mt * 16 + trow;
            const int col = n0 + colbase + nt * 8 + tcol;
            *(float2*)(pO + (size_t)row * D + col) =
                make_float2(acc[mt][nt][0], acc[mt][nt][1]);
            *(float2*)(pO + (size_t)(row + 8) * D + col) =
                make_float2(acc[mt][nt][2], acc[mt][nt][3]);
        }
    }
}

// ---------------------------------------------------------------------------
// softmax: one warp per row, barrier-free. Emits P fp32 + fp16.
// ---------------------------------------------------------------------------
__global__ void __launch_bounds__(256) softmax_kernel(float* __restrict__ attn) {
    const int wid = threadIdx.x >> 5, lid = threadIdx.x & 31;
    const size_t row = (size_t)blockIdx.x * 8 + wid;
    float* p = attn + row * L;
    __half* ph = g_ph + row * L;

    float4 v[8];
    #pragma unroll
    for (int i = 0; i < 8; i++) v[i] = ((const float4*)p)[lid + 32 * i];

    float m = neg_inf();
    #pragma unroll
    for (int i = 0; i < 8; i++) {
        m = fmaxf(m, fmaxf(fmaxf(v[i].x, v[i].y), fmaxf(v[i].z, v[i].w)));
    }
    #pragma unroll
    for (int o = 16; o > 0; o >>= 1) m = fmaxf(m, __shfl_xor_sync(0xffffffffu, m, o));

    if (m == neg_inf()) {
        const float4 z4 = make_float4(0.f, 0.f, 0.f, 0.f);
        const uint2 z2 = make_uint2(0u, 0u);
        #pragma unroll
        for (int i = 0; i < 8; i++) {
            ((float4*)p)[lid + 32 * i] = z4;
            ((uint2*)ph)[lid + 32 * i] = z2;
        }
        return;
    }

    float s = 0.0f;
    #pragma unroll
    for (int i = 0; i < 8; i++) {
        v[i].x = __expf(v[i].x - m);
        v[i].y = __expf(v[i].y - m);
        v[i].z = __expf(v[i].z - m);
        v[i].w = __expf(v[i].w - m);
        s += (v[i].x + v[i].y) + (v[i].z + v[i].w);
    }
    #pragma unroll
    for (int o = 16; o > 0; o >>= 1) s += __shfl_xor_sync(0xffffffffu, s, o);
    const float inv = 1.0f / s;

    #pragma unroll
    for (int i = 0; i < 8; i++) {
        v[i].x *= inv; v[i].y *= inv; v[i].z *= inv; v[i].w *= inv;
        ((float4*)p)[lid + 32 * i] = v[i];

        __half2 hp0 = __floats2half2_rn(v[i].x, v[i].y);
        __half2 hp1 = __floats2half2_rn(v[i].z, v[i].w);
        uint2 hu;
        hu.x = *(uint32_t*)&hp0;
        hu.y = *(uint32_t*)&hp1;
        ((uint2*)ph)[lid + 32 * i] = hu;
    }
}

// ---------------------------------------------------------------------------
// Launch
// ---------------------------------------------------------------------------
extern "C" void kernel_launch(void* const* d_in, const int* in_sizes, int n_in,
                              void* d_out, int out_size) {
    const float* q = (const float*)d_in[0];
    float* out  = (float*)d_out;
    float* attn = (float*)d_out + (size_t)B * L * D;

    void *qh, *ql, *qth, *ph;
    cudaGetSymbolAddress(&qh,  g_qh);
    cudaGetSymbolAddress(&ql,  g_ql);
    cudaGetSymbolAddress(&qth, g_qth);
    cudaGetSymbolAddress(&ph,  g_ph);

    cudaFuncSetAttribute(gemm_qqt_sym_kernel, cudaFuncAttributeMaxDynamicSharedMemorySize, G1_SMEM);
    cudaFuncSetAttribute(gemm_pv_kernel,      cudaFuncAttributeMaxDynamicSharedMemorySize, PV_SMEM);

    dim3 gs(D / 32, L / 32, B);
    split_q_kernel<<<gs, dim3(32, 8)>>>(q);

    dim3 g1(72, 1, B);
    gemm_qqt_sym_kernel<<<g1, 256, G1_SMEM>>>(
        (const __half*)qh, (const __half*)ql, attn);

    softmax_kernel<<<B * L / 8, 256>>>(attn);

    dim3 g2(D / 128, L / 64, B);
    gemm_pv_kernel<<<g2, 256, PV_SMEM>>>(
        (const __half*)ph, (const __half*)qth, out);
}